// round 10
// baseline (speedup 1.0000x reference)
#include <cuda_runtime.h>
#include <cstdint>

#define D_MODEL 1024
#define NHEAD   16
#define DK      64
#define BB      2
#define SEQ     2048
#define MROWS   (BB * SEQ)   // 4096
#define NBH     (BB * NHEAD) // 32

// attention tiling
#define QROWS 32
#define CHUNK 128
#define NCH   (SEQ / CHUNK)  // 16

// padded smem strides (u32 units)
#define KSTR  68             // K chunk [128 keys][64 d]   (key-major)
#define VSTR  132            // V chunk [64 d][128 keys]   (d-major)
#define QSTR  68             // Q tile  [32 rows][64 d]
#define PPAD  36             // per-warp P patch [16 rows][32 keys]
#define KBUF  (128 * KSTR)   // 8704
#define VBUF  (64 * VSTR)    // 8448

// projection GEMM strides
#define ASTR  20
#define BSTR  136

// ---------------- scratch (device globals) -----------------------------------
__device__ uint32_t g_qin[MROWS * D_MODEL];
__device__ uint32_t g_kin[MROWS * D_MODEL];
__device__ uint32_t g_vin[MROWS * D_MODEL];
__device__ uint32_t g_wqc[D_MODEL * D_MODEL];
__device__ uint32_t g_wkc[D_MODEL * D_MODEL];
__device__ uint32_t g_wvc[D_MODEL * D_MODEL];
__device__ uint32_t g_woc[D_MODEL * D_MODEL];
__device__ uint32_t g_qh [NBH * SEQ * DK];   // [bh][s][d] tf32, pre-scaled 1/8
__device__ uint32_t g_kh [NBH * SEQ * DK];   // [bh][s][d] tf32 (key-major)
__device__ uint32_t g_vT [NBH * DK * SEQ];   // [bh][d][s] tf32 (transposed)
__device__ uint32_t g_ctx[MROWS * D_MODEL];  // [b*S+s][h*64+d] tf32

// ---------------- helpers ----------------------------------------------------
__device__ __forceinline__ uint32_t f2tf(float x) {
    uint32_t u;
    asm("cvt.rna.tf32.f32 %0, %1;" : "=r"(u) : "f"(x));
    return u;
}

__device__ __forceinline__ void mma8(float* d, const uint32_t* a,
                                     uint32_t b0, uint32_t b1) {
    asm volatile(
        "mma.sync.aligned.m16n8k8.row.col.f32.tf32.tf32.f32 "
        "{%0,%1,%2,%3}, {%4,%5,%6,%7}, {%8,%9}, {%0,%1,%2,%3};"
        : "+f"(d[0]), "+f"(d[1]), "+f"(d[2]), "+f"(d[3])
        : "r"(a[0]), "r"(a[1]), "r"(a[2]), "r"(a[3]), "r"(b0), "r"(b1));
}

__device__ __forceinline__ void ldsm4(uint32_t* r, uint32_t saddr) {
    asm volatile(
        "ldmatrix.sync.aligned.m8n8.x4.shared.b16 {%0,%1,%2,%3}, [%4];"
        : "=r"(r[0]), "=r"(r[1]), "=r"(r[2]), "=r"(r[3]) : "r"(saddr));
}

__device__ __forceinline__ void cpa16(uint32_t dst, const void* src) {
    asm volatile("cp.async.cg.shared.global [%0], [%1], 16;"
                 :: "r"(dst), "l"(src) : "memory");
}
#define CPA_COMMIT() asm volatile("cp.async.commit_group;" ::: "memory")
#define CPA_WAIT0()  asm volatile("cp.async.wait_group 0;" ::: "memory")

// ---------------- pre-convert fp32 -> tf32 bits -------------------------------
__global__ void __launch_bounds__(256) cvt_inputs(
    const float* __restrict__ q, const float* __restrict__ k,
    const float* __restrict__ v)
{
    const float* src = (blockIdx.y == 0) ? q : (blockIdx.y == 1) ? k : v;
    uint32_t* dst = (blockIdx.y == 0) ? g_qin : (blockIdx.y == 1) ? g_kin : g_vin;
    const int i = (blockIdx.x * 256 + threadIdx.x) * 4;
    float4 f = *(const float4*)&src[i];
    uint4 o;
    o.x = f2tf(f.x); o.y = f2tf(f.y); o.z = f2tf(f.z); o.w = f2tf(f.w);
    *(uint4*)&dst[i] = o;
}

__global__ void __launch_bounds__(256) cvt_weights(
    const float* __restrict__ wq, const float* __restrict__ wk,
    const float* __restrict__ wv, const float* __restrict__ wo)
{
    const float* src = (blockIdx.y == 0) ? wq : (blockIdx.y == 1) ? wk
                     : (blockIdx.y == 2) ? wv : wo;
    uint32_t* dst = (blockIdx.y == 0) ? g_wqc : (blockIdx.y == 1) ? g_wkc
                  : (blockIdx.y == 2) ? g_wvc : g_woc;
    const int i = (blockIdx.x * 256 + threadIdx.x) * 4;
    float4 f = *(const float4*)&src[i];
    uint4 o;
    o.x = f2tf(f.x); o.y = f2tf(f.y); o.z = f2tf(f.z); o.w = f2tf(f.w);
    *(uint4*)&dst[i] = o;
}

// ---------------- tf32 tensor GEMM (unchanged) -------------------------------
__device__ __forceinline__ void gemm_tf32(
    const uint32_t* __restrict__ A, const uint32_t* __restrict__ W,
    const float* __restrict__ bias, void* __restrict__ outp,
    int mode, uint32_t* As, uint32_t* Bs)
{
    const int t    = threadIdx.x;
    const int lane = t & 31;
    const int w    = t >> 5;
    const int g    = lane >> 2;
    const int t4   = lane & 3;
    const int bm   = blockIdx.y * 128;
    const int bn   = blockIdx.x * 128;
    const int wm   = (w >> 1) * 32;
    const int wn   = (w & 1) * 64;

    const int a_m = t >> 1, a_c = (t & 1) * 8;
    const int w_k = t >> 4, w_c = (t & 15) * 8;

    const uint32_t* aptr = A + (size_t)(bm + a_m) * 1024 + a_c;
    const uint32_t* wptr = W + (size_t)w_k * 1024 + bn + w_c;

    float acc[2][8][4];
#pragma unroll
    for (int mt = 0; mt < 2; ++mt)
#pragma unroll
        for (int nt = 0; nt < 8; ++nt)
#pragma unroll
            for (int i = 0; i < 4; ++i) acc[mt][nt][i] = 0.f;

    uint4 ra0, ra1, rb0, rb1;

    ra0 = *(const uint4*)(aptr);
    ra1 = *(const uint4*)(aptr + 4);
    rb0 = *(const uint4*)(wptr);
    rb1 = *(const uint4*)(wptr + 4);
    *(uint4*)&As[a_m * ASTR + a_c]     = ra0;
    *(uint4*)&As[a_m * ASTR + a_c + 4] = ra1;
    *(uint4*)&Bs[w_k * BSTR + w_c]     = rb0;
    *(uint4*)&Bs[w_k * BSTR + w_c + 4] = rb1;
    __syncthreads();

    for (int it = 0; it < 64; ++it) {
        const int buf = it & 1;
        if (it < 63) {
            const int k0 = (it + 1) * 16;
            ra0 = *(const uint4*)(aptr + k0);
            ra1 = *(const uint4*)(aptr + k0 + 4);
            rb0 = *(const uint4*)(wptr + (size_t)k0 * 1024);
            rb1 = *(const uint4*)(wptr + (size_t)k0 * 1024 + 4);
        }
        const uint32_t* Ab = As + buf * (128 * ASTR);
        const uint32_t* Bb = Bs + buf * (16 * BSTR);
#pragma unroll
        for (int ks = 0; ks < 2; ++ks) {
            uint32_t af[2][4];
#pragma unroll
            for (int mt = 0; mt < 2; ++mt) {
                const int r0 = wm + mt * 16 + g;
                af[mt][0] = Ab[r0       * ASTR + ks * 8 + t4];
                af[mt][1] = Ab[(r0 + 8) * ASTR + ks * 8 + t4];
                af[mt][2] = Ab[r0       * ASTR + ks * 8 + t4 + 4];
                af[mt][3] = Ab[(r0 + 8) * ASTR + ks * 8 + t4 + 4];
            }
#pragma unroll
            for (int nt = 0; nt < 8; ++nt) {
                const int nc = wn + nt * 8 + g;
                uint32_t b0 = Bb[(ks * 8 + t4)     * BSTR + nc];
                uint32_t b1 = Bb[(ks * 8 + t4 + 4) * BSTR + nc];
                mma8(acc[0][nt], af[0], b0, b1);
                mma8(acc[1][nt], af[1], b0, b1);
            }
        }
        if (it < 63) {
            uint32_t* a_s = As + (buf ^ 1) * (128 * ASTR) + a_m * ASTR + a_c;
            *(uint4*)(a_s)     = ra0;
            *(uint4*)(a_s + 4) = ra1;
            uint32_t* b_s = Bs + (buf ^ 1) * (16 * BSTR) + w_k * BSTR + w_c;
            *(uint4*)(b_s)     = rb0;
            *(uint4*)(b_s + 4) = rb1;
        }
        __syncthreads();
    }

#pragma unroll
    for (int mt = 0; mt < 2; ++mt) {
        const int m0 = bm + wm + mt * 16 + g;
#pragma unroll
        for (int nt = 0; nt < 8; ++nt) {
            const int n0 = bn + wn + nt * 8 + 2 * t4;
            const float bz0 = bias[n0], bz1 = bias[n0 + 1];
            float v00 = acc[mt][nt][0] + bz0;
            float v01 = acc[mt][nt][1] + bz1;
            float v10 = acc[mt][nt][2] + bz0;
            float v11 = acc[mt][nt][3] + bz1;
            if (mode == 0) {
                float* out = (float*)outp;
                *(float2*)&out[(size_t)m0 * 1024 + n0]       = make_float2(v00, v01);
                *(float2*)&out[(size_t)(m0 + 8) * 1024 + n0] = make_float2(v10, v11);
            } else {
                uint32_t* out = (uint32_t*)outp;
                const int b0i = m0 >> 11, s0 = m0 & 2047;
                const int h = n0 >> 6, d = n0 & 63;
                const int bh = b0i * NHEAD + h;
                if (mode == 1) {
                    *(uint2*)&out[((size_t)bh * SEQ + s0) * DK + d] =
                        make_uint2(f2tf(v00 * 0.125f), f2tf(v01 * 0.125f));
                    *(uint2*)&out[((size_t)bh * SEQ + s0 + 8) * DK + d] =
                        make_uint2(f2tf(v10 * 0.125f), f2tf(v11 * 0.125f));
                } else if (mode == 3) {
                    *(uint2*)&out[((size_t)bh * SEQ + s0) * DK + d] =
                        make_uint2(f2tf(v00), f2tf(v01));
                    *(uint2*)&out[((size_t)bh * SEQ + s0 + 8) * DK + d] =
                        make_uint2(f2tf(v10), f2tf(v11));
                } else { // mode 2: transposed [bh][d][s]
                    uint32_t* ob = out + (size_t)bh * DK * SEQ;
                    ob[(size_t)d       * SEQ + s0]     = f2tf(v00);
                    ob[(size_t)(d + 1) * SEQ + s0]     = f2tf(v01);
                    ob[(size_t)d       * SEQ + s0 + 8] = f2tf(v10);
                    ob[(size_t)(d + 1) * SEQ + s0 + 8] = f2tf(v11);
                }
            }
        }
    }
}

__global__ void __launch_bounds__(256) qkv_gemm_p(
    const float* __restrict__ bq, const float* __restrict__ bk,
    const float* __restrict__ bv)
{
    __shared__ uint32_t As[2 * 128 * ASTR];
    __shared__ uint32_t Bs[2 * 16 * BSTR];
    const int z = blockIdx.z;
    const uint32_t* A    = (z == 0) ? g_qin : (z == 1) ? g_kin : g_vin;
    const uint32_t* W    = (z == 0) ? g_wqc : (z == 1) ? g_wkc : g_wvc;
    const float*    bias = (z == 0) ? bq    : (z == 1) ? bk    : bv;
    uint32_t* out        = (z == 0) ? g_qh  : (z == 1) ? g_kh  : g_vT;
    const int mode       = (z == 0) ? 1     : (z == 1) ? 3     : 2;
    gemm_tf32(A, W, bias, out, mode, As, Bs);
}

__global__ void __launch_bounds__(256) out_gemm(
    const float* __restrict__ bo, float* __restrict__ out)
{
    __shared__ uint32_t As[2 * 128 * ASTR];
    __shared__ uint32_t Bs[2 * 16 * BSTR];
    gemm_tf32(g_ctx, g_woc, bo, out, 0, As, Bs);
}

// ---------------- attention: single-pass, 256 thr, 2 CTAs/SM ------------------
// 8 warps = 2 m-groups (16 rows) x 4 key-groups (32 keys/chunk).
// Single-buffered K/V; inter-CTA overlap hides load + barrier latency.
__global__ void __launch_bounds__(256, 2) attn_k(float* __restrict__ attn_out)
{
    extern __shared__ uint32_t smu[];
    uint32_t* qs = smu;                    // 32*QSTR  = 2176
    uint32_t* ks = qs + 32 * QSTR;         // KBUF     = 8704 ([key][d])
    uint32_t* vs = ks + KBUF;              // VBUF     = 8448 ([d][key])
    uint32_t* pp = vs + VBUF;              // 8*16*PPAD = 4608
    float* stl = (float*)(pp + 8 * 16 * PPAD);   // 128
    float* fls = stl + 128;                      // 32

    const int t    = threadIdx.x;
    const int lane = t & 31;
    const int w    = t >> 5;       // 0..7
    const int g    = lane >> 2;
    const int t4   = lane & 3;
    const int mg   = w >> 2;       // 0..1 : rows mg*16..+15
    const int kg   = w & 3;        // 0..3 : keys kg*32..+31 within chunk
    const int bh   = blockIdx.y;
    const int q0   = blockIdx.x * QROWS;

    const uint32_t smem_b = (uint32_t)__cvta_generic_to_shared(smu);
    const uint32_t qs_b = smem_b;
    const uint32_t ks_b = smem_b + 32 * QSTR * 4;
    const uint32_t vs_b = ks_b + KBUF * 4;
    const uint32_t pp_b = vs_b + VBUF * 4;

    const uint32_t* kh  = g_kh + (size_t)bh * SEQ * DK;   // [s][d]
    const uint32_t* vT  = g_vT + (size_t)bh * DK * SEQ;   // [d][s]

    // cp.async per-thread indices (8 x 16B each for K and V)
    int kk_[8], kd_[8], vd_[8], vk_[8];
#pragma unroll
    for (int r = 0; r < 8; ++r) {
        int lin = r * 256 + t;
        kk_[r] = lin >> 4;  kd_[r] = (lin & 15) * 4;   // K: key 0..127, d
        vd_[r] = lin >> 5;  vk_[r] = (lin & 31) * 4;   // V: d 0..63, key
    }

    const int lrow8 = (lane & 7) + ((lane >> 4) << 3);   // 0..15
    const int lc4   = ((lane >> 3) & 1) * 4;             // 0 or 4

    // stage Q (32 rows x 64 d)
    {
        const uint32_t* qb = g_qh + ((size_t)bh * SEQ + q0) * DK;
        const int r = t >> 3, c4 = (t & 7) * 8;
        *(uint4*)&qs[r * QSTR + c4]     = *(const uint4*)&qb[r * DK + c4];
        *(uint4*)&qs[r * QSTR + c4 + 4] = *(const uint4*)&qb[r * DK + c4 + 4];
    }
    __syncthreads();

    // persistent Q A-fragments (rows mg*16..+15, all 8 k-blocks)
    uint32_t afr[8][4];
    {
        const uint32_t qlane = qs_b +
            ((mg * 16 + (lane & 15)) * QSTR + (lane >> 4) * 4) * 4;
#pragma unroll
        for (int kb = 0; kb < 8; ++kb) ldsm4(afr[kb], qlane + kb * 8 * 4);
    }

    const uint32_t kfrag = ks_b + ((kg * 32 + lrow8) * KSTR + lc4) * 4;
    const uint32_t vfrag = vs_b + (lrow8 * VSTR + kg * 32 + lc4) * 4;

    float lrow[2] = {0.f, 0.f};
    float oacc[8][4];
#pragma unroll
    for (int nb = 0; nb < 8; ++nb)
#pragma unroll
        for (int i = 0; i < 4; ++i) oacc[nb][i] = 0.f;

    float* attn_base = attn_out + ((size_t)bh * SEQ + q0) * SEQ;
    uint32_t* ppw = pp + w * 16 * PPAD;
    const uint32_t pplane = pp_b + w * 16 * PPAD * 4 +
        ((lane & 15) * PPAD + (lane >> 4) * 4) * 4;

    // ============== main loop (single-buffered K/V) ==============
    for (int c = 0; c < NCH; ++c) {
        __syncthreads();   // everyone done reading buffers from chunk c-1
#pragma unroll
        for (int r = 0; r < 8; ++r) {
            cpa16(ks_b + (kk_[r] * KSTR + kd_[r]) * 4,
                  kh + ((size_t)c * CHUNK + kk_[r]) * DK + kd_[r]);
            cpa16(vs_b + (vd_[r] * VSTR + vk_[r]) * 4,
                  vT + (size_t)vd_[r] * SEQ + c * CHUNK + vk_[r]);
        }
        CPA_COMMIT();
        CPA_WAIT0();
        __syncthreads();   // chunk c visible

        // scores: warp computes 16 rows x 32 keys over K=64
        float sacc[4][4];
#pragma unroll
        for (int nb = 0; nb < 4; ++nb)
#pragma unroll
            for (int i = 0; i < 4; ++i) sacc[nb][i] = 0.f;
#pragma unroll
        for (int kb = 0; kb < 8; ++kb) {
#pragma unroll
            for (int nq = 0; nq < 2; ++nq) {
                uint32_t b[4];
                ldsm4(b, kfrag + (nq * 16 * KSTR + kb * 8) * 4);
                mma8(sacc[nq * 2],     afr[kb], b[0], b[1]);
                mma8(sacc[nq * 2 + 1], afr[kb], b[2], b[3]);
            }
        }
        // u = exp(s); row sums; write u to patch + gmem
        float csum0 = 0.f, csum1 = 0.f;
#pragma unroll
        for (int nb = 0; nb < 4; ++nb) {
            const float u00 = __expf(sacc[nb][0]);
            const float u01 = __expf(sacc[nb][1]);
            const float u10 = __expf(sacc[nb][2]);
            const float u11 = __expf(sacc[nb][3]);
            csum0 += u00 + u01;
            csum1 += u10 + u11;
            const int pc = nb * 8 + 2 * t4;
            *(uint2*)&ppw[g * PPAD + pc]       = make_uint2(f2tf(u00), f2tf(u01));
            *(uint2*)&ppw[(g + 8) * PPAD + pc] = make_uint2(f2tf(u10), f2tf(u11));
            const int col = c * CHUNK + kg * 32 + pc;
            *(float2*)&attn_base[(size_t)(mg * 16 + g) * SEQ + col] =
                make_float2(u00, u01);
            *(float2*)&attn_base[(size_t)(mg * 16 + g + 8) * SEQ + col] =
                make_float2(u10, u11);
        }
        csum0 += __shfl_xor_sync(~0u, csum0, 1);
        csum0 += __shfl_xor_sync(~0u, csum0, 2);
        csum1 += __shfl_xor_sync(~0u, csum1, 1);
        csum1 += __shfl_xor_sync(~0u, csum1, 2);
        lrow[0] += csum0;
        lrow[1] += csum1;
        __syncwarp();

        // P @ V: A = own 16x32 patch, B = V[32 keys][64 d]
#pragma unroll
        for (int kb2 = 0; kb2 < 4; ++kb2) {
            uint32_t a[4];
            ldsm4(a, pplane + kb2 * 8 * 4);
#pragma unroll
            for (int np = 0; np < 4; ++np) {
                uint32_t b[4];
                ldsm4(b, vfrag + (np * 16 * VSTR + kb2 * 8) * 4);
                mma8(oacc[np * 2],     a, b[0], b[1]);
                mma8(oacc[np * 2 + 1], a, b[2], b[3]);
            }
        }
    }

    // ---- l reduce across 4 key-group warps ----
    if (t4 == 0) {
        stl[kg * 32 + mg * 16 + g]     = lrow[0];
        stl[kg * 32 + mg * 16 + g + 8] = lrow[1];
    }
    __syncthreads();
    if (t < 32) {
        float fl = 0.f;
#pragma unroll
        for (int q = 0; q < 4; ++q) fl += stl[q * 32 + t];
        fls[t] = 1.0f / fl;
    }
    __syncthreads();
    const float flv0 = fls[mg * 16 + g];
    const float flv1 = fls[mg * 16 + g + 8];

    // ---- in-place fixup: scale own u values by 1/l (L2-resident RMW) ----
#pragma unroll
    for (int c = 0; c < NCH; ++c) {
#pragma unroll
        for (int nb = 0; nb < 4; ++nb) {
            const int col = c * CHUNK + kg * 32 + nb * 8 + 2 * t4;
            float* a0 = &attn_base[(size_t)(mg * 16 + g) * SEQ + col];
            float* a1 = &attn_base[(size_t)(mg * 16 + g + 8) * SEQ + col];
            float2 v0 = __ldcg((const float2*)a0);
            float2 v1 = __ldcg((const float2*)a1);
            v0.x *= flv0; v0.y *= flv0;
            v1.x *= flv1; v1.y *= flv1;
            __stcs((float2*)a0, v0);
            __stcs((float2*)a1, v1);
        }
    }

    // ---- O reduce across 4 key-group warps per m-group ----
    __syncthreads();
    float* osm = (float*)ks;   // 8 warps x [16][68] = 8704 floats (fits KBUF)
#pragma unroll
    for (int nb = 0; nb < 8; ++nb) {
        const int oc = nb * 8 + 2 * t4;
        *(float2*)&osm[w * 1088 + g * 68 + oc]       = make_float2(oacc[nb][0], oacc[nb][1]);
        *(float2*)&osm[w * 1088 + (g + 8) * 68 + oc] = make_float2(oacc[nb][2], oacc[nb][3]);
    }
    __syncthreads();
    const int b = bh >> 4, h = bh & 15;
#pragma unroll
    for (int i = t; i < 2048; i += 256) {
        const int rr = i >> 6, d = i & 63;
        const int mg2 = rr >> 4, r16 = rr & 15;
        float s = 0.f;
#pragma unroll
        for (int q = 0; q < 4; ++q)
            s += osm[(mg2 * 4 + q) * 1088 + r16 * 68 + d];
        g_ctx[((size_t)b * SEQ + q0 + rr) * D_MODEL + h * DK + d] =
            f2tf(s * fls[rr]);
    }
}

// ---------------- launch -----------------------------------------------------
extern "C" void kernel_launch(void* const* d_in, const int* in_sizes, int n_in,
                              void* d_out, int out_size)
{
    (void)in_sizes; (void)n_in; (void)out_size;
    const float* q  = (const float*)d_in[0];
    const float* k  = (const float*)d_in[1];
    const float* v  = (const float*)d_in[2];
    const float* wq = (const float*)d_in[3];
    const float* bq = (const float*)d_in[4];
    const float* wk = (const float*)d_in[5];
    const float* bk = (const float*)d_in[6];
    const float* wv = (const float*)d_in[7];
    const float* bv = (const float*)d_in[8];
    const float* wo = (const float*)d_in[9];
    const float* bo = (const float*)d_in[10];

    float* out  = (float*)d_out;                       // [B,S,D]
    float* attn = out + (size_t)MROWS * D_MODEL;       // [B,H,S,S]

    const int smem = (32 * QSTR + KBUF + VBUF + 8 * 16 * PPAD + 160) * 4;  // ~96KB
    cudaFuncSetAttribute(attn_k, cudaFuncAttributeMaxDynamicSharedMemorySize, smem);

    cvt_inputs <<<dim3(MROWS * D_MODEL / (256 * 4), 3), 256>>>(q, k, v);
    cvt_weights<<<dim3(D_MODEL * D_MODEL / (256 * 4), 4), 256>>>(wq, wk, wv, wo);
    qkv_gemm_p<<<dim3(8, 32, 3), 256>>>(bq, bk, bv);
    attn_k<<<dim3(SEQ / QROWS, NBH), 256, smem>>>(attn);
    out_gemm<<<dim3(8, 32), 256>>>(bo, out);
}

// round 11
// speedup vs baseline: 1.1493x; 1.1493x over previous
#include <cuda_runtime.h>
#include <cstdint>

#define D_MODEL 1024
#define NHEAD   16
#define DK      64
#define BB      2
#define SEQ     2048
#define MROWS   (BB * SEQ)   // 4096
#define NBH     (BB * NHEAD) // 32

// attention tiling (R7 config)
#define QROWS 64
#define CHUNK 128
#define NCH   (SEQ / CHUNK)  // 16

// padded smem strides (u32 units)
#define KSTR  136            // K chunk [64 d][128 keys]
#define VSTR  72             // V chunk [128 keys][64 d]
#define QSTR  68             // Q tile [64 rows][64 d]
#define PPAD  36             // per-warp P patch [16 rows][32 keys]
#define KBUF  (64 * KSTR)    // 8704
#define VBUF  (128 * VSTR)   // 9216

// projection GEMM strides / pipeline
#define ASTR  20
#define BSTR  136
#define NST   3
#define ATILE (128 * ASTR)   // 2560
#define BTILE (16 * BSTR)    // 2176

// ---------------- scratch (device globals) -----------------------------------
__device__ uint32_t g_qin[MROWS * D_MODEL];
__device__ uint32_t g_kin[MROWS * D_MODEL];
__device__ uint32_t g_vin[MROWS * D_MODEL];
__device__ uint32_t g_wqc[D_MODEL * D_MODEL];
__device__ uint32_t g_wkc[D_MODEL * D_MODEL];
__device__ uint32_t g_wvc[D_MODEL * D_MODEL];
__device__ uint32_t g_woc[D_MODEL * D_MODEL];
__device__ uint32_t g_qh [NBH * SEQ * DK];   // [bh][s][d] tf32, pre-scaled 1/8
__device__ uint32_t g_kT [NBH * DK * SEQ];   // [bh][d][s] tf32
__device__ uint32_t g_vh [NBH * SEQ * DK];   // [bh][s][d] tf32
__device__ uint32_t g_ctx[MROWS * D_MODEL];  // [b*S+s][h*64+d] tf32

// ---------------- helpers ----------------------------------------------------
__device__ __forceinline__ uint32_t f2tf(float x) {
    uint32_t u;
    asm("cvt.rna.tf32.f32 %0, %1;" : "=r"(u) : "f"(x));
    return u;
}

__device__ __forceinline__ void mma8(float* d, const uint32_t* a,
                                     uint32_t b0, uint32_t b1) {
    asm volatile(
        "mma.sync.aligned.m16n8k8.row.col.f32.tf32.tf32.f32 "
        "{%0,%1,%2,%3}, {%4,%5,%6,%7}, {%8,%9}, {%0,%1,%2,%3};"
        : "+f"(d[0]), "+f"(d[1]), "+f"(d[2]), "+f"(d[3])
        : "r"(a[0]), "r"(a[1]), "r"(a[2]), "r"(a[3]), "r"(b0), "r"(b1));
}

__device__ __forceinline__ void ldsm4(uint32_t* r, uint32_t saddr) {
    asm volatile(
        "ldmatrix.sync.aligned.m8n8.x4.shared.b16 {%0,%1,%2,%3}, [%4];"
        : "=r"(r[0]), "=r"(r[1]), "=r"(r[2]), "=r"(r[3]) : "r"(saddr));
}

__device__ __forceinline__ void cpa16(uint32_t dst, const void* src) {
    asm volatile("cp.async.cg.shared.global [%0], [%1], 16;"
                 :: "r"(dst), "l"(src) : "memory");
}
#define CPA_COMMIT() asm volatile("cp.async.commit_group;" ::: "memory")
#define CPA_WAIT1()  asm volatile("cp.async.wait_group 1;" ::: "memory")
#define CPA_WAIT0()  asm volatile("cp.async.wait_group 0;" ::: "memory")

// ---------------- pre-convert fp32 -> tf32 bits -------------------------------
__global__ void __launch_bounds__(256) cvt_inputs(
    const float* __restrict__ q, const float* __restrict__ k,
    const float* __restrict__ v)
{
    const float* src = (blockIdx.y == 0) ? q : (blockIdx.y == 1) ? k : v;
    uint32_t* dst = (blockIdx.y == 0) ? g_qin : (blockIdx.y == 1) ? g_kin : g_vin;
    const int i = (blockIdx.x * 256 + threadIdx.x) * 4;
    float4 f = *(const float4*)&src[i];
    uint4 o;
    o.x = f2tf(f.x); o.y = f2tf(f.y); o.z = f2tf(f.z); o.w = f2tf(f.w);
    *(uint4*)&dst[i] = o;
}

__global__ void __launch_bounds__(256) cvt_weights(
    const float* __restrict__ wq, const float* __restrict__ wk,
    const float* __restrict__ wv, const float* __restrict__ wo)
{
    const float* src = (blockIdx.y == 0) ? wq : (blockIdx.y == 1) ? wk
                     : (blockIdx.y == 2) ? wv : wo;
    uint32_t* dst = (blockIdx.y == 0) ? g_wqc : (blockIdx.y == 1) ? g_wkc
                  : (blockIdx.y == 2) ? g_wvc : g_woc;
    const int i = (blockIdx.x * 256 + threadIdx.x) * 4;
    float4 f = *(const float4*)&src[i];
    uint4 o;
    o.x = f2tf(f.x); o.y = f2tf(f.y); o.z = f2tf(f.z); o.w = f2tf(f.w);
    *(uint4*)&dst[i] = o;
}

// ---------------- tf32 tensor GEMM: 3-stage cp.async pipeline -----------------
// C[4096,1024] = A @ W + bias. CTA 128x128, kt=16, 256 thr (8 warps 4m x 2n).
// One barrier per k-iter; loads land 2 stages ahead via cp.async.
__device__ __forceinline__ void gemm_tf32(
    const uint32_t* __restrict__ A, const uint32_t* __restrict__ W,
    const float* __restrict__ bias, void* __restrict__ outp,
    int mode, uint32_t* As, uint32_t* Bs)
{
    const int t    = threadIdx.x;
    const int lane = t & 31;
    const int w    = t >> 5;
    const int g    = lane >> 2;
    const int t4   = lane & 3;
    const int bm   = blockIdx.y * 128;
    const int bn   = blockIdx.x * 128;
    const int wm   = (w >> 1) * 32;
    const int wn   = (w & 1) * 64;

    const int a_m = t >> 1, a_c = (t & 1) * 8;
    const int w_k = t >> 4, w_c = (t & 15) * 8;

    const uint32_t* aptr = A + (size_t)(bm + a_m) * 1024 + a_c;
    const uint32_t* wptr = W + (size_t)w_k * 1024 + bn + w_c;

    const uint32_t as_b = (uint32_t)__cvta_generic_to_shared(As);
    const uint32_t bs_b = (uint32_t)__cvta_generic_to_shared(Bs);
    const uint32_t a_off = (a_m * ASTR + a_c) * 4;
    const uint32_t b_off = (w_k * BSTR + w_c) * 4;

    float acc[2][8][4];
#pragma unroll
    for (int mt = 0; mt < 2; ++mt)
#pragma unroll
        for (int nt = 0; nt < 8; ++nt)
#pragma unroll
            for (int i = 0; i < 4; ++i) acc[mt][nt][i] = 0.f;

    // prologue: stages 0, 1
#pragma unroll
    for (int s = 0; s < 2; ++s) {
        const int k0 = s * 16;
        cpa16(as_b + s * (ATILE * 4) + a_off,      aptr + k0);
        cpa16(as_b + s * (ATILE * 4) + a_off + 16, aptr + k0 + 4);
        cpa16(bs_b + s * (BTILE * 4) + b_off,      wptr + (size_t)k0 * 1024);
        cpa16(bs_b + s * (BTILE * 4) + b_off + 16, wptr + (size_t)k0 * 1024 + 4);
        CPA_COMMIT();
    }

    for (int it = 0; it < 64; ++it) {
        if (it < 62) { CPA_WAIT1(); } else { CPA_WAIT0(); }
        __syncthreads();
        const int stage = it % NST;
        const uint32_t* Ab = As + stage * ATILE;
        const uint32_t* Bb = Bs + stage * BTILE;
#pragma unroll
        for (int ks = 0; ks < 2; ++ks) {
            uint32_t af[2][4];
#pragma unroll
            for (int mt = 0; mt < 2; ++mt) {
                const int r0 = wm + mt * 16 + g;
                af[mt][0] = Ab[r0       * ASTR + ks * 8 + t4];
                af[mt][1] = Ab[(r0 + 8) * ASTR + ks * 8 + t4];
                af[mt][2] = Ab[r0       * ASTR + ks * 8 + t4 + 4];
                af[mt][3] = Ab[(r0 + 8) * ASTR + ks * 8 + t4 + 4];
            }
#pragma unroll
            for (int nt = 0; nt < 8; ++nt) {
                const int nc = wn + nt * 8 + g;
                uint32_t b0 = Bb[(ks * 8 + t4)     * BSTR + nc];
                uint32_t b1 = Bb[(ks * 8 + t4 + 4) * BSTR + nc];
                mma8(acc[0][nt], af[0], b0, b1);
                mma8(acc[1][nt], af[1], b0, b1);
            }
        }
        if (it < 62) {
            const int s2 = (it + 2) % NST;
            const int k0 = (it + 2) * 16;
            cpa16(as_b + s2 * (ATILE * 4) + a_off,      aptr + k0);
            cpa16(as_b + s2 * (ATILE * 4) + a_off + 16, aptr + k0 + 4);
            cpa16(bs_b + s2 * (BTILE * 4) + b_off,      wptr + (size_t)k0 * 1024);
            cpa16(bs_b + s2 * (BTILE * 4) + b_off + 16, wptr + (size_t)k0 * 1024 + 4);
            CPA_COMMIT();
        }
    }

    // ---- epilogue ----
#pragma unroll
    for (int mt = 0; mt < 2; ++mt) {
        const int m0 = bm + wm + mt * 16 + g;
#pragma unroll
        for (int nt = 0; nt < 8; ++nt) {
            const int n0 = bn + wn + nt * 8 + 2 * t4;
            const float bz0 = bias[n0], bz1 = bias[n0 + 1];
            float v00 = acc[mt][nt][0] + bz0;
            float v01 = acc[mt][nt][1] + bz1;
            float v10 = acc[mt][nt][2] + bz0;
            float v11 = acc[mt][nt][3] + bz1;
            if (mode == 0) {
                float* out = (float*)outp;
                *(float2*)&out[(size_t)m0 * 1024 + n0]       = make_float2(v00, v01);
                *(float2*)&out[(size_t)(m0 + 8) * 1024 + n0] = make_float2(v10, v11);
            } else {
                uint32_t* out = (uint32_t*)outp;
                const int b0i = m0 >> 11, s0 = m0 & 2047;
                const int h = n0 >> 6, d = n0 & 63;
                const int bh = b0i * NHEAD + h;
                if (mode == 1) {
                    *(uint2*)&out[((size_t)bh * SEQ + s0) * DK + d] =
                        make_uint2(f2tf(v00 * 0.125f), f2tf(v01 * 0.125f));
                    *(uint2*)&out[((size_t)bh * SEQ + s0 + 8) * DK + d] =
                        make_uint2(f2tf(v10 * 0.125f), f2tf(v11 * 0.125f));
                } else if (mode == 3) {
                    *(uint2*)&out[((size_t)bh * SEQ + s0) * DK + d] =
                        make_uint2(f2tf(v00), f2tf(v01));
                    *(uint2*)&out[((size_t)bh * SEQ + s0 + 8) * DK + d] =
                        make_uint2(f2tf(v10), f2tf(v11));
                } else { // mode 2: kT [bh][d][s]
                    uint32_t* ob = out + (size_t)bh * DK * SEQ;
                    ob[(size_t)d       * SEQ + s0]     = f2tf(v00);
                    ob[(size_t)(d + 1) * SEQ + s0]     = f2tf(v01);
                    ob[(size_t)d       * SEQ + s0 + 8] = f2tf(v10);
                    ob[(size_t)(d + 1) * SEQ + s0 + 8] = f2tf(v11);
                }
            }
        }
    }
}

__global__ void __launch_bounds__(256, 2) qkv_gemm_p(
    const float* __restrict__ bq, const float* __restrict__ bk,
    const float* __restrict__ bv)
{
    extern __shared__ uint32_t gsm[];
    uint32_t* As = gsm;
    uint32_t* Bs = gsm + NST * ATILE;
    const int z = blockIdx.z;
    const uint32_t* A    = (z == 0) ? g_qin : (z == 1) ? g_kin : g_vin;
    const uint32_t* W    = (z == 0) ? g_wqc : (z == 1) ? g_wkc : g_wvc;
    const float*    bias = (z == 0) ? bq    : (z == 1) ? bk    : bv;
    uint32_t* out        = (z == 0) ? g_qh  : (z == 1) ? g_kT  : g_vh;
    gemm_tf32(A, W, bias, out, z + 1, As, Bs);
}

__global__ void __launch_bounds__(256, 2) out_gemm(
    const float* __restrict__ bo, float* __restrict__ out)
{
    extern __shared__ uint32_t gsm[];
    uint32_t* As = gsm;
    uint32_t* Bs = gsm + NST * ATILE;
    gemm_tf32(g_ctx, g_woc, bo, out, 0, As, Bs);
}

// ---------------- attention: R7 config (best: 494us) --------------------------
// 512 thr = 16 warps. warp = (mg = w>>2: 16 rows, kg = w&3: 32 keys/chunk).
// Q A-frags persistent in regs; P consumed from per-warp smem patch; O in regs.
__global__ void __launch_bounds__(512) attn_k(float* __restrict__ attn_out)
{
    extern __shared__ uint32_t smu[];
    uint32_t* qs = smu;                    // 64*QSTR           = 4352
    uint32_t* ks = qs + 64 * QSTR;         // 2*KBUF            = 17408
    uint32_t* vs = ks + 2 * KBUF;          // 2*VBUF            = 18432
    uint32_t* pp = vs + 2 * VBUF;          // 16*16*PPAD        = 9216
    float* stm = (float*)(pp + 16 * 16 * PPAD);   // 256
    float* stl = stm + 256;                       // 256
    float* fmm = stl + 256;                       // 64
    float* fls = fmm + 64;                        // 64

    const int t    = threadIdx.x;
    const int lane = t & 31;
    const int w    = t >> 5;       // 0..15
    const int g    = lane >> 2;
    const int t4   = lane & 3;
    const int mg   = w >> 2;       // m-group: rows mg*16..+15
    const int kg   = w & 3;        // key-group: keys kg*32..+31 within chunk
    const int bh   = blockIdx.y;
    const int q0   = blockIdx.x * QROWS;

    const uint32_t smem_b = (uint32_t)__cvta_generic_to_shared(smu);
    const uint32_t qs_b = smem_b;
    const uint32_t ks_b = smem_b + 64 * QSTR * 4;
    const uint32_t vs_b = ks_b + 2 * KBUF * 4;
    const uint32_t pp_b = vs_b + 2 * VBUF * 4;

    const uint32_t* kT  = g_kT + (size_t)bh * DK * SEQ;
    const uint32_t* vbg = g_vh + (size_t)bh * SEQ * DK;

    int kd[4], kj[4], vk[4], vd[4];
#pragma unroll
    for (int r = 0; r < 4; ++r) {
        int lin = r * 512 + t;
        kd[r] = lin >> 5;  kj[r] = (lin & 31) * 4;
        vk[r] = lin >> 4;  vd[r] = (lin & 15) * 4;
    }

    // stage Q
    {
        const uint32_t* qb = g_qh + ((size_t)bh * SEQ + q0) * DK;
        const int r = t >> 3, c4 = (t & 7) * 8;
        *(uint4*)&qs[r * QSTR + c4]     = *(const uint4*)&qb[r * DK + c4];
        *(uint4*)&qs[r * QSTR + c4 + 4] = *(const uint4*)&qb[r * DK + c4 + 4];
    }
    // prologue: K chunk 0 -> buf 0
#pragma unroll
    for (int r = 0; r < 4; ++r)
        cpa16(ks_b + (kd[r] * KSTR + kj[r]) * 4, kT + (size_t)kd[r] * SEQ + kj[r]);
    CPA_COMMIT();
    __syncthreads();   // qs visible

    // persistent Q A-fragments (rows mg*16..+15, all 8 k-blocks)
    uint32_t afr[8][4];
    {
        const uint32_t qlane = qs_b +
            ((mg * 16 + (lane & 15)) * QSTR + (lane >> 4) * 4) * 4;
#pragma unroll
        for (int kb = 0; kb < 8; ++kb) ldsm4(afr[kb], qlane + kb * 8 * 4);
    }

    // ============== pass 1: row stats ==============
    float mrow[2] = {-1e30f, -1e30f}, lrow[2] = {0.f, 0.f};

    for (int c = 0; c < NCH; ++c) {
        __syncthreads();   // all warps done with buf (c+1)&1 from iter c-1
        if (c < NCH - 1) {
#pragma unroll
            for (int r = 0; r < 4; ++r)
                cpa16(ks_b + (((c + 1) & 1) * KBUF + kd[r] * KSTR + kj[r]) * 4,
                      kT + (size_t)kd[r] * SEQ + (c + 1) * CHUNK + kj[r]);
            CPA_COMMIT();
            CPA_WAIT1();
        } else {
            CPA_WAIT0();
        }
        __syncthreads();   // chunk c visible to all

        const uint32_t* kb_ = ks + (c & 1) * KBUF;
        float sacc[4][4];
#pragma unroll
        for (int nb = 0; nb < 4; ++nb)
#pragma unroll
            for (int i = 0; i < 4; ++i) sacc[nb][i] = 0.f;
#pragma unroll
        for (int kb = 0; kb < 8; ++kb) {
#pragma unroll
            for (int nb = 0; nb < 4; ++nb) {
                const int jc = kg * 32 + nb * 8 + g;
                uint32_t b0 = kb_[(kb * 8 + t4)     * KSTR + jc];
                uint32_t b1 = kb_[(kb * 8 + t4 + 4) * KSTR + jc];
                mma8(sacc[nb], afr[kb], b0, b1);
            }
        }
        // online stats over this warp's 32 keys
#pragma unroll
        for (int sl = 0; sl < 2; ++sl) {
            float vm = -1e30f;
#pragma unroll
            for (int nb = 0; nb < 4; ++nb)
                vm = fmaxf(vm, fmaxf(sacc[nb][sl * 2], sacc[nb][sl * 2 + 1]));
            vm = fmaxf(vm, __shfl_xor_sync(~0u, vm, 1));
            vm = fmaxf(vm, __shfl_xor_sync(~0u, vm, 2));
            const float mn = fmaxf(mrow[sl], vm);
            float cs = 0.f;
#pragma unroll
            for (int nb = 0; nb < 4; ++nb)
                cs += __expf(sacc[nb][sl * 2] - mn) + __expf(sacc[nb][sl * 2 + 1] - mn);
            cs += __shfl_xor_sync(~0u, cs, 1);
            cs += __shfl_xor_sync(~0u, cs, 2);
            lrow[sl] = lrow[sl] * __expf(mrow[sl] - mn) + cs;
            mrow[sl] = mn;
        }
    }

    // cross-key-group reduce
    if (t4 == 0) {
        stm[kg * 64 + mg * 16 + g]     = mrow[0];
        stm[kg * 64 + mg * 16 + g + 8] = mrow[1];
        stl[kg * 64 + mg * 16 + g]     = lrow[0];
        stl[kg * 64 + mg * 16 + g + 8] = lrow[1];
    }
    __syncthreads();
    if (t < 64) {
        float fm = -1e30f;
#pragma unroll
        for (int q = 0; q < 4; ++q) fm = fmaxf(fm, stm[q * 64 + t]);
        float fl = 0.f;
#pragma unroll
        for (int q = 0; q < 4; ++q) fl += stl[q * 64 + t] * __expf(stm[q * 64 + t] - fm);
        fmm[t] = fm;
        fls[t] = 1.0f / fl;
    }
    __syncthreads();
    const float fmv0 = fmm[mg * 16 + g],     flv0 = fls[mg * 16 + g];
    const float fmv1 = fmm[mg * 16 + g + 8], flv1 = fls[mg * 16 + g + 8];
    __syncthreads();

    // ============== pass 2: P write + P@V ==============
#pragma unroll
    for (int r = 0; r < 4; ++r) {
        cpa16(ks_b + (kd[r] * KSTR + kj[r]) * 4, kT + (size_t)kd[r] * SEQ + kj[r]);
        cpa16(vs_b + (vk[r] * VSTR + vd[r]) * 4, vbg + (size_t)vk[r] * DK + vd[r]);
    }
    CPA_COMMIT();

    float oacc[8][4];
#pragma unroll
    for (int nb = 0; nb < 8; ++nb)
#pragma unroll
        for (int i = 0; i < 4; ++i) oacc[nb][i] = 0.f;

    float* attn_base = attn_out + ((size_t)bh * SEQ + q0) * SEQ;
    uint32_t* ppw = pp + w * 16 * PPAD;
    const uint32_t pplane = pp_b + w * 16 * PPAD * 4 +
        ((lane & 15) * PPAD + (lane >> 4) * 4) * 4;

    for (int c = 0; c < NCH; ++c) {
        __syncthreads();
        if (c < NCH - 1) {
#pragma unroll
            for (int r = 0; r < 4; ++r) {
                cpa16(ks_b + (((c + 1) & 1) * KBUF + kd[r] * KSTR + kj[r]) * 4,
                      kT + (size_t)kd[r] * SEQ + (c + 1) * CHUNK + kj[r]);
                cpa16(vs_b + (((c + 1) & 1) * VBUF + vk[r] * VSTR + vd[r]) * 4,
                      vbg + ((size_t)(c + 1) * CHUNK + vk[r]) * DK + vd[r]);
            }
            CPA_COMMIT();
            CPA_WAIT1();
        } else {
            CPA_WAIT0();
        }
        __syncthreads();

        // scores
        const uint32_t* kb_ = ks + (c & 1) * KBUF;
        float sacc[4][4];
#pragma unroll
        for (int nb = 0; nb < 4; ++nb)
#pragma unroll
            for (int i = 0; i < 4; ++i) sacc[nb][i] = 0.f;
#pragma unroll
        for (int kb = 0; kb < 8; ++kb) {
#pragma unroll
            for (int nb = 0; nb < 4; ++nb) {
                const int jc = kg * 32 + nb * 8 + g;
                uint32_t b0 = kb_[(kb * 8 + t4)     * KSTR + jc];
                uint32_t b1 = kb_[(kb * 8 + t4 + 4) * KSTR + jc];
                mma8(sacc[nb], afr[kb], b0, b1);
            }
        }
        // p = exp(s - m) * invl: direct gmem write + tf32 patch for PV
#pragma unroll
        for (int nb = 0; nb < 4; ++nb) {
            const float p00 = __expf(sacc[nb][0] - fmv0) * flv0;
            const float p01 = __expf(sacc[nb][1] - fmv0) * flv0;
            const float p10 = __expf(sacc[nb][2] - fmv1) * flv1;
            const float p11 = __expf(sacc[nb][3] - fmv1) * flv1;
            const int pc = nb * 8 + 2 * t4;
            *(uint2*)&ppw[g * PPAD + pc]       = make_uint2(f2tf(p00), f2tf(p01));
            *(uint2*)&ppw[(g + 8) * PPAD + pc] = make_uint2(f2tf(p10), f2tf(p11));
            const int col = c * CHUNK + kg * 32 + pc;
            __stcs((float2*)&attn_base[(size_t)(mg * 16 + g) * SEQ + col],
                   make_float2(p00, p01));
            __stcs((float2*)&attn_base[(size_t)(mg * 16 + g + 8) * SEQ + col],
                   make_float2(p10, p11));
        }
        __syncwarp();

        // P @ V: warp's own 16x32 P block x V(32 keys, 64 d)
        const uint32_t* vb_ = vs + (c & 1) * VBUF;
#pragma unroll
        for (int kb2 = 0; kb2 < 4; ++kb2) {
            uint32_t a[4];
            ldsm4(a, pplane + kb2 * 8 * 4);
            const int kbase = kg * 32 + kb2 * 8;
#pragma unroll
            for (int nb = 0; nb < 8; ++nb) {
                uint32_t b0 = vb_[(kbase + t4)     * VSTR + nb * 8 + g];
                uint32_t b1 = vb_[(kbase + t4 + 4) * VSTR + nb * 8 + g];
                mma8(oacc[nb], a, b0, b1);
            }
        }
    }

    // ---- O reduce across 4 key-group warps per m-group ----
    __syncthreads();
    float* osm = (float*)vs;   // 16 warps x [16][68]
#pragma unroll
    for (int nb = 0; nb < 8; ++nb) {
        const int oc = nb * 8 + 2 * t4;
        *(float2*)&osm[w * 1088 + g * 68 + oc]       = make_float2(oacc[nb][0], oacc[nb][1]);
        *(float2*)&osm[w * 1088 + (g + 8) * 68 + oc] = make_float2(oacc[nb][2], oacc[nb][3]);
    }
    __syncthreads();
    const int b = bh >> 4, h = bh & 15;
#pragma unroll
    for (int i = t; i < 4096; i += 512) {
        const int rr = i >> 6, d = i & 63;
        const int mg2 = rr >> 4, r16 = rr & 15;
        float s = 0.f;
#pragma unroll
        for (int q = 0; q < 4; ++q)
            s += osm[(mg2 * 4 + q) * 1088 + r16 * 68 + d];
        g_ctx[((size_t)b * SEQ + q0 + rr) * D_MODEL + h * DK + d] = f2tf(s);
    }
}

// ---------------- launch -----------------------------------------------------
extern "C" void kernel_launch(void* const* d_in, const int* in_sizes, int n_in,
                              void* d_out, int out_size)
{
    (void)in_sizes; (void)n_in; (void)out_size;
    const float* q  = (const float*)d_in[0];
    const float* k  = (const float*)d_in[1];
    const float* v  = (const float*)d_in[2];
    const float* wq = (const float*)d_in[3];
    const float* bq = (const float*)d_in[4];
    const float* wk = (const float*)d_in[5];
    const float* bk = (const float*)d_in[6];
    const float* wv = (const float*)d_in[7];
    const float* bv = (const float*)d_in[8];
    const float* wo = (const float*)d_in[9];
    const float* bo = (const float*)d_in[10];

    float* out  = (float*)d_out;                       // [B,S,D]
    float* attn = out + (size_t)MROWS * D_MODEL;       // [B,H,S,S]

    const int asmem = (64 * QSTR + 2 * KBUF + 2 * VBUF + 16 * 16 * PPAD + 640) * 4;
    cudaFuncSetAttribute(attn_k, cudaFuncAttributeMaxDynamicSharedMemorySize, asmem);
    const int gsmem = NST * (ATILE + BTILE) * 4;   // 56832 B
    cudaFuncSetAttribute(qkv_gemm_p, cudaFuncAttributeMaxDynamicSharedMemorySize, gsmem);
    cudaFuncSetAttribute(out_gemm,   cudaFuncAttributeMaxDynamicSharedMemorySize, gsmem);

    cvt_inputs <<<dim3(MROWS * D_MODEL / (256 * 4), 3), 256>>>(q, k, v);
    cvt_weights<<<dim3(D_MODEL * D_MODEL / (256 * 4), 4), 256>>>(wq, wk, wv, wo);
    qkv_gemm_p<<<dim3(8, 32, 3), 256, gsmem>>>(bq, bk, bv);
    attn_k<<<dim3(SEQ / QROWS, NBH), 512, asmem>>>(attn);
    out_gemm<<<dim3(8, 32), 256, gsmem>>>(bo, out);
}

// round 12
// speedup vs baseline: 1.2015x; 1.0454x over previous
#include <cuda_runtime.h>
#include <cstdint>

#define D_MODEL 1024
#define NHEAD   16
#define DK      64
#define BB      2
#define SEQ     2048
#define MROWS   (BB * SEQ)   // 4096
#define NBH     (BB * NHEAD) // 32

// attention tiling
#define QROWS 64
#define CHUNK 128
#define NCH   (SEQ / CHUNK)  // 16

// padded smem strides (u32 units)
#define KSTR  136            // K chunk [64 d][128 keys]
#define VSTR  72             // V chunk [128 keys][64 d]
#define QSTR  68             // Q tile [64 rows][64 d]
#define PPAD  36             // per-warp P patch [16 rows][32 keys]
#define KBUF  (64 * KSTR)    // 8704
#define VBUF  (128 * VSTR)   // 9216

// projection GEMM strides / pipeline
#define ASTR  20
#define BSTR  136
#define NST   3
#define ATILE (128 * ASTR)   // 2560
#define BTILE (16 * BSTR)    // 2176

// ---------------- scratch (device globals) -----------------------------------
__device__ uint32_t g_qin[MROWS * D_MODEL];
__device__ uint32_t g_kin[MROWS * D_MODEL];
__device__ uint32_t g_vin[MROWS * D_MODEL];
__device__ uint32_t g_wqc[D_MODEL * D_MODEL];
__device__ uint32_t g_wkc[D_MODEL * D_MODEL];
__device__ uint32_t g_wvc[D_MODEL * D_MODEL];
__device__ uint32_t g_woc[D_MODEL * D_MODEL];
__device__ uint32_t g_qh [NBH * SEQ * DK];   // [bh][s][d] tf32, pre-scaled 1/8
__device__ uint32_t g_kT [NBH * DK * SEQ];   // [bh][d][s] tf32
__device__ uint32_t g_vh [NBH * SEQ * DK];   // [bh][s][d] tf32
__device__ uint32_t g_ctx[MROWS * D_MODEL];  // [b*S+s][h*64+d] tf32

// ---------------- helpers ----------------------------------------------------
__device__ __forceinline__ uint32_t f2tf(float x) {
    uint32_t u;
    asm("cvt.rna.tf32.f32 %0, %1;" : "=r"(u) : "f"(x));
    return u;
}

__device__ __forceinline__ void mma8(float* d, const uint32_t* a,
                                     uint32_t b0, uint32_t b1) {
    asm volatile(
        "mma.sync.aligned.m16n8k8.row.col.f32.tf32.tf32.f32 "
        "{%0,%1,%2,%3}, {%4,%5,%6,%7}, {%8,%9}, {%0,%1,%2,%3};"
        : "+f"(d[0]), "+f"(d[1]), "+f"(d[2]), "+f"(d[3])
        : "r"(a[0]), "r"(a[1]), "r"(a[2]), "r"(a[3]), "r"(b0), "r"(b1));
}

__device__ __forceinline__ void ldsm4(uint32_t* r, uint32_t saddr) {
    asm volatile(
        "ldmatrix.sync.aligned.m8n8.x4.shared.b16 {%0,%1,%2,%3}, [%4];"
        : "=r"(r[0]), "=r"(r[1]), "=r"(r[2]), "=r"(r[3]) : "r"(saddr));
}

__device__ __forceinline__ void cpa16(uint32_t dst, const void* src) {
    asm volatile("cp.async.cg.shared.global [%0], [%1], 16;"
                 :: "r"(dst), "l"(src) : "memory");
}
#define CPA_COMMIT() asm volatile("cp.async.commit_group;" ::: "memory")
#define CPA_WAIT1()  asm volatile("cp.async.wait_group 1;" ::: "memory")
#define CPA_WAIT0()  asm volatile("cp.async.wait_group 0;" ::: "memory")

// ---------------- pre-convert fp32 -> tf32 bits -------------------------------
__global__ void __launch_bounds__(256) cvt_inputs(
    const float* __restrict__ q, const float* __restrict__ k,
    const float* __restrict__ v)
{
    const float* src = (blockIdx.y == 0) ? q : (blockIdx.y == 1) ? k : v;
    uint32_t* dst = (blockIdx.y == 0) ? g_qin : (blockIdx.y == 1) ? g_kin : g_vin;
    const int i = (blockIdx.x * 256 + threadIdx.x) * 4;
    float4 f = *(const float4*)&src[i];
    uint4 o;
    o.x = f2tf(f.x); o.y = f2tf(f.y); o.z = f2tf(f.z); o.w = f2tf(f.w);
    *(uint4*)&dst[i] = o;
}

__global__ void __launch_bounds__(256) cvt_weights(
    const float* __restrict__ wq, const float* __restrict__ wk,
    const float* __restrict__ wv, const float* __restrict__ wo)
{
    const float* src = (blockIdx.y == 0) ? wq : (blockIdx.y == 1) ? wk
                     : (blockIdx.y == 2) ? wv : wo;
    uint32_t* dst = (blockIdx.y == 0) ? g_wqc : (blockIdx.y == 1) ? g_wkc
                  : (blockIdx.y == 2) ? g_wvc : g_woc;
    const int i = (blockIdx.x * 256 + threadIdx.x) * 4;
    float4 f = *(const float4*)&src[i];
    uint4 o;
    o.x = f2tf(f.x); o.y = f2tf(f.y); o.z = f2tf(f.z); o.w = f2tf(f.w);
    *(uint4*)&dst[i] = o;
}

// ---------------- tf32 tensor GEMM: 3-stage cp.async pipeline (R11) -----------
__device__ __forceinline__ void gemm_tf32(
    const uint32_t* __restrict__ A, const uint32_t* __restrict__ W,
    const float* __restrict__ bias, void* __restrict__ outp,
    int mode, uint32_t* As, uint32_t* Bs)
{
    const int t    = threadIdx.x;
    const int lane = t & 31;
    const int w    = t >> 5;
    const int g    = lane >> 2;
    const int t4   = lane & 3;
    const int bm   = blockIdx.y * 128;
    const int bn   = blockIdx.x * 128;
    const int wm   = (w >> 1) * 32;
    const int wn   = (w & 1) * 64;

    const int a_m = t >> 1, a_c = (t & 1) * 8;
    const int w_k = t >> 4, w_c = (t & 15) * 8;

    const uint32_t* aptr = A + (size_t)(bm + a_m) * 1024 + a_c;
    const uint32_t* wptr = W + (size_t)w_k * 1024 + bn + w_c;

    const uint32_t as_b = (uint32_t)__cvta_generic_to_shared(As);
    const uint32_t bs_b = (uint32_t)__cvta_generic_to_shared(Bs);
    const uint32_t a_off = (a_m * ASTR + a_c) * 4;
    const uint32_t b_off = (w_k * BSTR + w_c) * 4;

    float acc[2][8][4];
#pragma unroll
    for (int mt = 0; mt < 2; ++mt)
#pragma unroll
        for (int nt = 0; nt < 8; ++nt)
#pragma unroll
            for (int i = 0; i < 4; ++i) acc[mt][nt][i] = 0.f;

#pragma unroll
    for (int s = 0; s < 2; ++s) {
        const int k0 = s * 16;
        cpa16(as_b + s * (ATILE * 4) + a_off,      aptr + k0);
        cpa16(as_b + s * (ATILE * 4) + a_off + 16, aptr + k0 + 4);
        cpa16(bs_b + s * (BTILE * 4) + b_off,      wptr + (size_t)k0 * 1024);
        cpa16(bs_b + s * (BTILE * 4) + b_off + 16, wptr + (size_t)k0 * 1024 + 4);
        CPA_COMMIT();
    }

    for (int it = 0; it < 64; ++it) {
        if (it < 62) { CPA_WAIT1(); } else { CPA_WAIT0(); }
        __syncthreads();
        const int stage = it % NST;
        const uint32_t* Ab = As + stage * ATILE;
        const uint32_t* Bb = Bs + stage * BTILE;
#pragma unroll
        for (int ks = 0; ks < 2; ++ks) {
            uint32_t af[2][4];
#pragma unroll
            for (int mt = 0; mt < 2; ++mt) {
                const int r0 = wm + mt * 16 + g;
                af[mt][0] = Ab[r0       * ASTR + ks * 8 + t4];
                af[mt][1] = Ab[(r0 + 8) * ASTR + ks * 8 + t4];
                af[mt][2] = Ab[r0       * ASTR + ks * 8 + t4 + 4];
                af[mt][3] = Ab[(r0 + 8) * ASTR + ks * 8 + t4 + 4];
            }
#pragma unroll
            for (int nt = 0; nt < 8; ++nt) {
                const int nc = wn + nt * 8 + g;
                uint32_t b0 = Bb[(ks * 8 + t4)     * BSTR + nc];
                uint32_t b1 = Bb[(ks * 8 + t4 + 4) * BSTR + nc];
                mma8(acc[0][nt], af[0], b0, b1);
                mma8(acc[1][nt], af[1], b0, b1);
            }
        }
        if (it < 62) {
            const int s2 = (it + 2) % NST;
            const int k0 = (it + 2) * 16;
            cpa16(as_b + s2 * (ATILE * 4) + a_off,      aptr + k0);
            cpa16(as_b + s2 * (ATILE * 4) + a_off + 16, aptr + k0 + 4);
            cpa16(bs_b + s2 * (BTILE * 4) + b_off,      wptr + (size_t)k0 * 1024);
            cpa16(bs_b + s2 * (BTILE * 4) + b_off + 16, wptr + (size_t)k0 * 1024 + 4);
            CPA_COMMIT();
        }
    }

#pragma unroll
    for (int mt = 0; mt < 2; ++mt) {
        const int m0 = bm + wm + mt * 16 + g;
#pragma unroll
        for (int nt = 0; nt < 8; ++nt) {
            const int n0 = bn + wn + nt * 8 + 2 * t4;
            const float bz0 = bias[n0], bz1 = bias[n0 + 1];
            float v00 = acc[mt][nt][0] + bz0;
            float v01 = acc[mt][nt][1] + bz1;
            float v10 = acc[mt][nt][2] + bz0;
            float v11 = acc[mt][nt][3] + bz1;
            if (mode == 0) {
                float* out = (float*)outp;
                *(float2*)&out[(size_t)m0 * 1024 + n0]       = make_float2(v00, v01);
                *(float2*)&out[(size_t)(m0 + 8) * 1024 + n0] = make_float2(v10, v11);
            } else {
                uint32_t* out = (uint32_t*)outp;
                const int b0i = m0 >> 11, s0 = m0 & 2047;
                const int h = n0 >> 6, d = n0 & 63;
                const int bh = b0i * NHEAD + h;
                if (mode == 1) {
                    *(uint2*)&out[((size_t)bh * SEQ + s0) * DK + d] =
                        make_uint2(f2tf(v00 * 0.125f), f2tf(v01 * 0.125f));
                    *(uint2*)&out[((size_t)bh * SEQ + s0 + 8) * DK + d] =
                        make_uint2(f2tf(v10 * 0.125f), f2tf(v11 * 0.125f));
                } else if (mode == 3) {
                    *(uint2*)&out[((size_t)bh * SEQ + s0) * DK + d] =
                        make_uint2(f2tf(v00), f2tf(v01));
                    *(uint2*)&out[((size_t)bh * SEQ + s0 + 8) * DK + d] =
                        make_uint2(f2tf(v10), f2tf(v11));
                } else { // mode 2: kT [bh][d][s]
                    uint32_t* ob = out + (size_t)bh * DK * SEQ;
                    ob[(size_t)d       * SEQ + s0]     = f2tf(v00);
                    ob[(size_t)(d + 1) * SEQ + s0]     = f2tf(v01);
                    ob[(size_t)d       * SEQ + s0 + 8] = f2tf(v10);
                    ob[(size_t)(d + 1) * SEQ + s0 + 8] = f2tf(v11);
                }
            }
        }
    }
}

__global__ void __launch_bounds__(256, 2) qkv_gemm_p(
    const float* __restrict__ bq, const float* __restrict__ bk,
    const float* __restrict__ bv)
{
    extern __shared__ uint32_t gsm[];
    uint32_t* As = gsm;
    uint32_t* Bs = gsm + NST * ATILE;
    const int z = blockIdx.z;
    const uint32_t* A    = (z == 0) ? g_qin : (z == 1) ? g_kin : g_vin;
    const uint32_t* W    = (z == 0) ? g_wqc : (z == 1) ? g_wkc : g_wvc;
    const float*    bias = (z == 0) ? bq    : (z == 1) ? bk    : bv;
    uint32_t* out        = (z == 0) ? g_qh  : (z == 1) ? g_kT  : g_vh;
    gemm_tf32(A, W, bias, out, z + 1, As, Bs);
}

__global__ void __launch_bounds__(256, 2) out_gemm(
    const float* __restrict__ bo, float* __restrict__ out)
{
    extern __shared__ uint32_t gsm[];
    uint32_t* As = gsm;
    uint32_t* Bs = gsm + NST * ATILE;
    gemm_tf32(g_ctx, g_woc, bo, out, 0, As, Bs);
}

// ---------------- attention: single-pass no-max, 1 barrier/chunk --------------
// 512 thr = 16 warps. warp = (mg = w>>2: 16 rows, kg = w&3: 32 keys/chunk).
// u = exp(s) unnormalized; L2-resident float4 fixup scales by 1/l at the end.
__global__ void __launch_bounds__(512) attn_k(float* __restrict__ attn_out)
{
    extern __shared__ uint32_t smu[];
    uint32_t* qs = smu;                    // 64*QSTR           = 4352
    uint32_t* ks = qs + 64 * QSTR;         // 2*KBUF            = 17408
    uint32_t* vs = ks + 2 * KBUF;          // 2*VBUF            = 18432
    uint32_t* pp = vs + 2 * VBUF;          // 16*16*PPAD        = 9216
    float* stl = (float*)(pp + 16 * 16 * PPAD);   // 256
    float* fls = stl + 256;                       // 64

    const int t    = threadIdx.x;
    const int lane = t & 31;
    const int w    = t >> 5;       // 0..15
    const int g    = lane >> 2;
    const int t4   = lane & 3;
    const int mg   = w >> 2;       // m-group: rows mg*16..+15
    const int kg   = w & 3;        // key-group: keys kg*32..+31 within chunk
    const int bh   = blockIdx.y;
    const int q0   = blockIdx.x * QROWS;

    const uint32_t smem_b = (uint32_t)__cvta_generic_to_shared(smu);
    const uint32_t qs_b = smem_b;
    const uint32_t ks_b = smem_b + 64 * QSTR * 4;
    const uint32_t vs_b = ks_b + 2 * KBUF * 4;
    const uint32_t pp_b = vs_b + 2 * VBUF * 4;

    const uint32_t* kT  = g_kT + (size_t)bh * DK * SEQ;
    const uint32_t* vbg = g_vh + (size_t)bh * SEQ * DK;

    int kd[4], kj[4], vk[4], vd[4];
#pragma unroll
    for (int r = 0; r < 4; ++r) {
        int lin = r * 512 + t;
        kd[r] = lin >> 5;  kj[r] = (lin & 31) * 4;
        vk[r] = lin >> 4;  vd[r] = (lin & 15) * 4;
    }

    // stage Q + issue chunk-0 loads into buf 0
    {
        const uint32_t* qb = g_qh + ((size_t)bh * SEQ + q0) * DK;
        const int r = t >> 3, c4 = (t & 7) * 8;
        *(uint4*)&qs[r * QSTR + c4]     = *(const uint4*)&qb[r * DK + c4];
        *(uint4*)&qs[r * QSTR + c4 + 4] = *(const uint4*)&qb[r * DK + c4 + 4];
    }
#pragma unroll
    for (int r = 0; r < 4; ++r) {
        cpa16(ks_b + (kd[r] * KSTR + kj[r]) * 4, kT + (size_t)kd[r] * SEQ + kj[r]);
        cpa16(vs_b + (vk[r] * VSTR + vd[r]) * 4, vbg + (size_t)vk[r] * DK + vd[r]);
    }
    CPA_COMMIT();
    __syncthreads();   // qs visible

    // persistent Q A-fragments (rows mg*16..+15, all 8 k-blocks)
    uint32_t afr[8][4];
    {
        const uint32_t qlane = qs_b +
            ((mg * 16 + (lane & 15)) * QSTR + (lane >> 4) * 4) * 4;
#pragma unroll
        for (int kb = 0; kb < 8; ++kb) ldsm4(afr[kb], qlane + kb * 8 * 4);
    }

    float lrow[2] = {0.f, 0.f};
    float oacc[8][4];
#pragma unroll
    for (int nb = 0; nb < 8; ++nb)
#pragma unroll
        for (int i = 0; i < 4; ++i) oacc[nb][i] = 0.f;

    float* attn_base = attn_out + ((size_t)bh * SEQ + q0) * SEQ;
    uint32_t* ppw = pp + w * 16 * PPAD;
    const uint32_t pplane = pp_b + w * 16 * PPAD * 4 +
        ((lane & 15) * PPAD + (lane >> 4) * 4) * 4;

    // ============== single main loop: 1 barrier per chunk ==============
    for (int c = 0; c < NCH; ++c) {
        CPA_WAIT0();       // this thread's loads(c) landed
        __syncthreads();   // all threads' loads(c) visible; compute(c-1) done everywhere
        if (c < NCH - 1) { // issue loads(c+1) into the buffer freed by compute(c-1)
#pragma unroll
            for (int r = 0; r < 4; ++r) {
                cpa16(ks_b + (((c + 1) & 1) * KBUF + kd[r] * KSTR + kj[r]) * 4,
                      kT + (size_t)kd[r] * SEQ + (c + 1) * CHUNK + kj[r]);
                cpa16(vs_b + (((c + 1) & 1) * VBUF + vk[r] * VSTR + vd[r]) * 4,
                      vbg + ((size_t)(c + 1) * CHUNK + vk[r]) * DK + vd[r]);
            }
            CPA_COMMIT();
        }

        // scores: 16 rows x 32 keys, K=64
        const uint32_t* kb_ = ks + (c & 1) * KBUF;
        float sacc[4][4];
#pragma unroll
        for (int nb = 0; nb < 4; ++nb)
#pragma unroll
            for (int i = 0; i < 4; ++i) sacc[nb][i] = 0.f;
#pragma unroll
        for (int kb = 0; kb < 8; ++kb) {
#pragma unroll
            for (int nb = 0; nb < 4; ++nb) {
                const int jc = kg * 32 + nb * 8 + g;
                uint32_t b0 = kb_[(kb * 8 + t4)     * KSTR + jc];
                uint32_t b1 = kb_[(kb * 8 + t4 + 4) * KSTR + jc];
                mma8(sacc[nb], afr[kb], b0, b1);
            }
        }

        // u = exp(s); row sums; write u (unnormalized, default stores -> L2)
        float csum0 = 0.f, csum1 = 0.f;
#pragma unroll
        for (int nb = 0; nb < 4; ++nb) {
            const float u00 = __expf(sacc[nb][0]);
            const float u01 = __expf(sacc[nb][1]);
            const float u10 = __expf(sacc[nb][2]);
            const float u11 = __expf(sacc[nb][3]);
            csum0 += u00 + u01;
            csum1 += u10 + u11;
            const int pc = nb * 8 + 2 * t4;
            *(uint2*)&ppw[g * PPAD + pc]       = make_uint2(f2tf(u00), f2tf(u01));
            *(uint2*)&ppw[(g + 8) * PPAD + pc] = make_uint2(f2tf(u10), f2tf(u11));
            const int col = c * CHUNK + kg * 32 + pc;
            *(float2*)&attn_base[(size_t)(mg * 16 + g) * SEQ + col] =
                make_float2(u00, u01);
            *(float2*)&attn_base[(size_t)(mg * 16 + g + 8) * SEQ + col] =
                make_float2(u10, u11);
        }
        csum0 += __shfl_xor_sync(~0u, csum0, 1);
        csum0 += __shfl_xor_sync(~0u, csum0, 2);
        csum1 += __shfl_xor_sync(~0u, csum1, 1);
        csum1 += __shfl_xor_sync(~0u, csum1, 2);
        lrow[0] += csum0;
        lrow[1] += csum1;
        __syncwarp();

        // P @ V: warp's own 16x32 u block x V(32 keys, 64 d)
        const uint32_t* vb_ = vs + (c & 1) * VBUF;
#pragma unroll
        for (int kb2 = 0; kb2 < 4; ++kb2) {
            uint32_t a[4];
            ldsm4(a, pplane + kb2 * 8 * 4);
            const int kbase = kg * 32 + kb2 * 8;
#pragma unroll
            for (int nb = 0; nb < 8; ++nb) {
                uint32_t b0 = vb_[(kbase + t4)     * VSTR + nb * 8 + g];
                uint32_t b1 = vb_[(kbase + t4 + 4) * VSTR + nb * 8 + g];
                mma8(oacc[nb], a, b0, b1);
            }
        }
    }

    // ---- l reduce across 4 key-group warps ----
    if (t4 == 0) {
        stl[kg * 64 + mg * 16 + g]     = lrow[0];
        stl[kg * 64 + mg * 16 + g + 8] = lrow[1];
    }
    __syncthreads();
    if (t < 64) {
        float fl = 0.f;
#pragma unroll
        for (int q = 0; q < 4; ++q) fl += stl[q * 64 + t];
        fls[t] = 1.0f / fl;
    }
    __syncthreads();

    // ---- in-place fixup: scale u by 1/l (float4, L2-resident) ----
#pragma unroll 4
    for (int i = t; i < 64 * 512; i += 512) {     // 512 float4 per row
        const int row = i >> 9;
        const int c4  = (i & 511) * 4;
        float4 v = __ldcg((const float4*)&attn_base[(size_t)row * SEQ + c4]);
        const float s = fls[row];
        v.x *= s; v.y *= s; v.z *= s; v.w *= s;
        __stcs((float4*)&attn_base[(size_t)row * SEQ + c4], v);
    }

    // ---- O reduce across 4 key-group warps per m-group (scale by 1/l) ----
    __syncthreads();
    float* osm = (float*)vs;   // 16 warps x [16][68] = 17408 floats
#pragma unroll
    for (int nb = 0; nb < 8; ++nb) {
        const int oc = nb * 8 + 2 * t4;
        *(float2*)&osm[w * 1088 + g * 68 + oc]       = make_float2(oacc[nb][0], oacc[nb][1]);
        *(float2*)&osm[w * 1088 + (g + 8) * 68 + oc] = make_float2(oacc[nb][2], oacc[nb][3]);
    }
    __syncthreads();
    const int b = bh >> 4, h = bh & 15;
#pragma unroll
    for (int i = t; i < 4096; i += 512) {
        const int rr = i >> 6, d = i & 63;
        const int mg2 = rr >> 4, r16 = rr & 15;
        float s = 0.f;
#pragma unroll
        for (int q = 0; q < 4; ++q)
            s += osm[(mg2 * 4 + q) * 1088 + r16 * 68 + d];
        g_ctx[((size_t)b * SEQ + q0 + rr) * D_MODEL + h * DK + d] =
            f2tf(s * fls[rr]);
    }
}

// ---------------- launch -----------------------------------------------------
extern "C" void kernel_launch(void* const* d_in, const int* in_sizes, int n_in,
                              void* d_out, int out_size)
{
    (void)in_sizes; (void)n_in; (void)out_size;
    const float* q  = (const float*)d_in[0];
    const float* k  = (const float*)d_in[1];
    const float* v  = (const float*)d_in[2];
    const float* wq = (const float*)d_in[3];
    const float* bq = (const float*)d_in[4];
    const float* wk = (const float*)d_in[5];
    const float* bk = (const float*)d_in[6];
    const float* wv = (const float*)d_in[7];
    const float* bv = (const float*)d_in[8];
    const float* wo = (const float*)d_in[9];
    const float* bo = (const float*)d_in[10];

    float* out  = (float*)d_out;                       // [B,S,D]
    float* attn = out + (size_t)MROWS * D_MODEL;       // [B,H,S,S]

    const int asmem = (64 * QSTR + 2 * KBUF + 2 * VBUF + 16 * 16 * PPAD + 320) * 4;
    cudaFuncSetAttribute(attn_k, cudaFuncAttributeMaxDynamicSharedMemorySize, asmem);
    const int gsmem = NST * (ATILE + BTILE) * 4;   // 56832 B
    cudaFuncSetAttribute(qkv_gemm_p, cudaFuncAttributeMaxDynamicSharedMemorySize, gsmem);
    cudaFuncSetAttribute(out_gemm,   cudaFuncAttributeMaxDynamicSharedMemorySize, gsmem);

    cvt_inputs <<<dim3(MROWS * D_MODEL / (256 * 4), 3), 256>>>(q, k, v);
    cvt_weights<<<dim3(D_MODEL * D_MODEL / (256 * 4), 4), 256>>>(wq, wk, wv, wo);
    qkv_gemm_p<<<dim3(8, 32, 3), 256, gsmem>>>(bq, bk, bv);
    attn_k<<<dim3(SEQ / QROWS, NBH), 512, asmem>>>(attn);
    out_gemm<<<dim3(8, 32), 256, gsmem>>>(bo, out);
}

// round 13
// speedup vs baseline: 1.5351x; 1.2776x over previous
#include <cuda_runtime.h>
#include <cuda_fp16.h>
#include <cstdint>

#define D_MODEL 1024
#define NHEAD   16
#define DK      64
#define BB      2
#define SEQ     2048
#define MROWS   (BB * SEQ)   // 4096
#define NBH     (BB * NHEAD) // 32

// attention tiling
#define QROWS 64
#define CHUNK 128
#define NCH   (SEQ / CHUNK)  // 16

// smem strides in HALVES (2B units)
#define QSTRH 72             // Q tile  [64 rows][64 d]
#define KSTRH 72             // K chunk [128 keys][64 d]
#define VSTRH 72             // V chunk [128 keys][64 d]
#define KBUFB (128 * KSTRH * 2)   // 18432 B per K buffer
#define VBUFB (128 * VSTRH * 2)   // 18432 B per V buffer

// projection GEMM strides / pipeline (tf32, unchanged)
#define ASTR  20
#define BSTR  136
#define NST   3
#define ATILE (128 * ASTR)   // 2560
#define BTILE (16 * BSTR)    // 2176

// ---------------- scratch (device globals) -----------------------------------
__device__ uint32_t g_qin[MROWS * D_MODEL];
__device__ uint32_t g_kin[MROWS * D_MODEL];
__device__ uint32_t g_vin[MROWS * D_MODEL];
__device__ uint32_t g_wqc[D_MODEL * D_MODEL];
__device__ uint32_t g_wkc[D_MODEL * D_MODEL];
__device__ uint32_t g_wvc[D_MODEL * D_MODEL];
__device__ uint32_t g_woc[D_MODEL * D_MODEL];
__device__ __half   g_qh [NBH * SEQ * DK];   // [bh][s][d] fp16, pre-scaled 1/8
__device__ __half   g_kh [NBH * SEQ * DK];   // [bh][s][d] fp16
__device__ __half   g_vh [NBH * SEQ * DK];   // [bh][s][d] fp16
__device__ uint32_t g_ctx[MROWS * D_MODEL];  // [b*S+s][h*64+d] tf32

// ---------------- helpers ----------------------------------------------------
__device__ __forceinline__ uint32_t f2tf(float x) {
    uint32_t u;
    asm("cvt.rna.tf32.f32 %0, %1;" : "=r"(u) : "f"(x));
    return u;
}

__device__ __forceinline__ uint32_t pack2h(float a, float b) {
    __half2 h = __floats2half2_rn(a, b);
    return *(uint32_t*)&h;
}

// tf32 m16n8k8 (projection GEMMs)
__device__ __forceinline__ void mma8(float* d, const uint32_t* a,
                                     uint32_t b0, uint32_t b1) {
    asm volatile(
        "mma.sync.aligned.m16n8k8.row.col.f32.tf32.tf32.f32 "
        "{%0,%1,%2,%3}, {%4,%5,%6,%7}, {%8,%9}, {%0,%1,%2,%3};"
        : "+f"(d[0]), "+f"(d[1]), "+f"(d[2]), "+f"(d[3])
        : "r"(a[0]), "r"(a[1]), "r"(a[2]), "r"(a[3]), "r"(b0), "r"(b1));
}

// fp16 m16n8k16 (attention)
__device__ __forceinline__ void mmah(float* d, const uint32_t* a,
                                     uint32_t b0, uint32_t b1) {
    asm volatile(
        "mma.sync.aligned.m16n8k16.row.col.f32.f16.f16.f32 "
        "{%0,%1,%2,%3}, {%4,%5,%6,%7}, {%8,%9}, {%0,%1,%2,%3};"
        : "+f"(d[0]), "+f"(d[1]), "+f"(d[2]), "+f"(d[3])
        : "r"(a[0]), "r"(a[1]), "r"(a[2]), "r"(a[3]), "r"(b0), "r"(b1));
}

__device__ __forceinline__ void ldsm4(uint32_t* r, uint32_t saddr) {
    asm volatile(
        "ldmatrix.sync.aligned.m8n8.x4.shared.b16 {%0,%1,%2,%3}, [%4];"
        : "=r"(r[0]), "=r"(r[1]), "=r"(r[2]), "=r"(r[3]) : "r"(saddr));
}

__device__ __forceinline__ void ldsm4t(uint32_t* r, uint32_t saddr) {
    asm volatile(
        "ldmatrix.sync.aligned.m8n8.x4.trans.shared.b16 {%0,%1,%2,%3}, [%4];"
        : "=r"(r[0]), "=r"(r[1]), "=r"(r[2]), "=r"(r[3]) : "r"(saddr));
}

__device__ __forceinline__ void cpa16(uint32_t dst, const void* src) {
    asm volatile("cp.async.cg.shared.global [%0], [%1], 16;"
                 :: "r"(dst), "l"(src) : "memory");
}
#define CPA_COMMIT() asm volatile("cp.async.commit_group;" ::: "memory")
#define CPA_WAIT1()  asm volatile("cp.async.wait_group 1;" ::: "memory")
#define CPA_WAIT0()  asm volatile("cp.async.wait_group 0;" ::: "memory")

// ---------------- pre-convert fp32 -> tf32 bits (for GEMMs) -------------------
__global__ void __launch_bounds__(256) cvt_inputs(
    const float* __restrict__ q, const float* __restrict__ k,
    const float* __restrict__ v)
{
    const float* src = (blockIdx.y == 0) ? q : (blockIdx.y == 1) ? k : v;
    uint32_t* dst = (blockIdx.y == 0) ? g_qin : (blockIdx.y == 1) ? g_kin : g_vin;
    const int i = (blockIdx.x * 256 + threadIdx.x) * 4;
    float4 f = *(const float4*)&src[i];
    uint4 o;
    o.x = f2tf(f.x); o.y = f2tf(f.y); o.z = f2tf(f.z); o.w = f2tf(f.w);
    *(uint4*)&dst[i] = o;
}

__global__ void __launch_bounds__(256) cvt_weights(
    const float* __restrict__ wq, const float* __restrict__ wk,
    const float* __restrict__ wv, const float* __restrict__ wo)
{
    const float* src = (blockIdx.y == 0) ? wq : (blockIdx.y == 1) ? wk
                     : (blockIdx.y == 2) ? wv : wo;
    uint32_t* dst = (blockIdx.y == 0) ? g_wqc : (blockIdx.y == 1) ? g_wkc
                  : (blockIdx.y == 2) ? g_wvc : g_woc;
    const int i = (blockIdx.x * 256 + threadIdx.x) * 4;
    float4 f = *(const float4*)&src[i];
    uint4 o;
    o.x = f2tf(f.x); o.y = f2tf(f.y); o.z = f2tf(f.z); o.w = f2tf(f.w);
    *(uint4*)&dst[i] = o;
}

// ---------------- tf32 tensor GEMM: 3-stage cp.async pipeline -----------------
// mode 0: fp32 row-major out; mode 1: fp16 qh (*0.125); mode 3: fp16 natural.
__device__ __forceinline__ void gemm_tf32(
    const uint32_t* __restrict__ A, const uint32_t* __restrict__ W,
    const float* __restrict__ bias, void* __restrict__ outp,
    int mode, uint32_t* As, uint32_t* Bs)
{
    const int t    = threadIdx.x;
    const int lane = t & 31;
    const int w    = t >> 5;
    const int g    = lane >> 2;
    const int t4   = lane & 3;
    const int bm   = blockIdx.y * 128;
    const int bn   = blockIdx.x * 128;
    const int wm   = (w >> 1) * 32;
    const int wn   = (w & 1) * 64;

    const int a_m = t >> 1, a_c = (t & 1) * 8;
    const int w_k = t >> 4, w_c = (t & 15) * 8;

    const uint32_t* aptr = A + (size_t)(bm + a_m) * 1024 + a_c;
    const uint32_t* wptr = W + (size_t)w_k * 1024 + bn + w_c;

    const uint32_t as_b = (uint32_t)__cvta_generic_to_shared(As);
    const uint32_t bs_b = (uint32_t)__cvta_generic_to_shared(Bs);
    const uint32_t a_off = (a_m * ASTR + a_c) * 4;
    const uint32_t b_off = (w_k * BSTR + w_c) * 4;

    float acc[2][8][4];
#pragma unroll
    for (int mt = 0; mt < 2; ++mt)
#pragma unroll
        for (int nt = 0; nt < 8; ++nt)
#pragma unroll
            for (int i = 0; i < 4; ++i) acc[mt][nt][i] = 0.f;

#pragma unroll
    for (int s = 0; s < 2; ++s) {
        const int k0 = s * 16;
        cpa16(as_b + s * (ATILE * 4) + a_off,      aptr + k0);
        cpa16(as_b + s * (ATILE * 4) + a_off + 16, aptr + k0 + 4);
        cpa16(bs_b + s * (BTILE * 4) + b_off,      wptr + (size_t)k0 * 1024);
        cpa16(bs_b + s * (BTILE * 4) + b_off + 16, wptr + (size_t)k0 * 1024 + 4);
        CPA_COMMIT();
    }

    for (int it = 0; it < 64; ++it) {
        if (it < 62) { CPA_WAIT1(); } else { CPA_WAIT0(); }
        __syncthreads();
        const int stage = it % NST;
        const uint32_t* Ab = As + stage * ATILE;
        const uint32_t* Bb = Bs + stage * BTILE;
#pragma unroll
        for (int ks = 0; ks < 2; ++ks) {
            uint32_t af[2][4];
#pragma unroll
            for (int mt = 0; mt < 2; ++mt) {
                const int r0 = wm + mt * 16 + g;
                af[mt][0] = Ab[r0       * ASTR + ks * 8 + t4];
                af[mt][1] = Ab[(r0 + 8) * ASTR + ks * 8 + t4];
                af[mt][2] = Ab[r0       * ASTR + ks * 8 + t4 + 4];
                af[mt][3] = Ab[(r0 + 8) * ASTR + ks * 8 + t4 + 4];
            }
#pragma unroll
            for (int nt = 0; nt < 8; ++nt) {
                const int nc = wn + nt * 8 + g;
                uint32_t b0 = Bb[(ks * 8 + t4)     * BSTR + nc];
                uint32_t b1 = Bb[(ks * 8 + t4 + 4) * BSTR + nc];
                mma8(acc[0][nt], af[0], b0, b1);
                mma8(acc[1][nt], af[1], b0, b1);
            }
        }
        if (it < 62) {
            const int s2 = (it + 2) % NST;
            const int k0 = (it + 2) * 16;
            cpa16(as_b + s2 * (ATILE * 4) + a_off,      aptr + k0);
            cpa16(as_b + s2 * (ATILE * 4) + a_off + 16, aptr + k0 + 4);
            cpa16(bs_b + s2 * (BTILE * 4) + b_off,      wptr + (size_t)k0 * 1024);
            cpa16(bs_b + s2 * (BTILE * 4) + b_off + 16, wptr + (size_t)k0 * 1024 + 4);
            CPA_COMMIT();
        }
    }

#pragma unroll
    for (int mt = 0; mt < 2; ++mt) {
        const int m0 = bm + wm + mt * 16 + g;
#pragma unroll
        for (int nt = 0; nt < 8; ++nt) {
            const int n0 = bn + wn + nt * 8 + 2 * t4;
            const float bz0 = bias[n0], bz1 = bias[n0 + 1];
            float v00 = acc[mt][nt][0] + bz0;
            float v01 = acc[mt][nt][1] + bz1;
            float v10 = acc[mt][nt][2] + bz0;
            float v11 = acc[mt][nt][3] + bz1;
            if (mode == 0) {
                float* out = (float*)outp;
                *(float2*)&out[(size_t)m0 * 1024 + n0]       = make_float2(v00, v01);
                *(float2*)&out[(size_t)(m0 + 8) * 1024 + n0] = make_float2(v10, v11);
            } else {
                __half* out = (__half*)outp;
                const int b0i = m0 >> 11, s0 = m0 & 2047;
                const int h = n0 >> 6, d = n0 & 63;
                const int bh = b0i * NHEAD + h;
                const float sc = (mode == 1) ? 0.125f : 1.0f;
                *(__half2*)&out[((size_t)bh * SEQ + s0) * DK + d] =
                    __floats2half2_rn(v00 * sc, v01 * sc);
                *(__half2*)&out[((size_t)bh * SEQ + s0 + 8) * DK + d] =
                    __floats2half2_rn(v10 * sc, v11 * sc);
            }
        }
    }
}

__global__ void __launch_bounds__(256, 2) qkv_gemm_p(
    const float* __restrict__ bq, const float* __restrict__ bk,
    const float* __restrict__ bv)
{
    extern __shared__ uint32_t gsm[];
    uint32_t* As = gsm;
    uint32_t* Bs = gsm + NST * ATILE;
    const int z = blockIdx.z;
    const uint32_t* A    = (z == 0) ? g_qin : (z == 1) ? g_kin : g_vin;
    const uint32_t* W    = (z == 0) ? g_wqc : (z == 1) ? g_wkc : g_wvc;
    const float*    bias = (z == 0) ? bq    : (z == 1) ? bk    : bv;
    void* out            = (z == 0) ? (void*)g_qh : (z == 1) ? (void*)g_kh : (void*)g_vh;
    gemm_tf32(A, W, bias, out, (z == 0) ? 1 : 3, As, Bs);
}

__global__ void __launch_bounds__(256, 2) out_gemm(
    const float* __restrict__ bo, float* __restrict__ out)
{
    extern __shared__ uint32_t gsm[];
    uint32_t* As = gsm;
    uint32_t* Bs = gsm + NST * ATILE;
    gemm_tf32(g_ctx, g_woc, bo, out, 0, As, Bs);
}

// ---------------- attention: fp16 single-pass, P in registers -----------------
// 512 thr = 16 warps. warp = (mg = w>>2: 16 rows, kg = w&3: 32 keys/chunk).
__global__ void __launch_bounds__(512) attn_k(float* __restrict__ attn_out)
{
    extern __shared__ char smc[];
    __half* qs = (__half*)smc;               // 64*QSTRH halves = 9216 B
    __half* ks = qs + 64 * QSTRH;            // 2 bufs = 36864 B
    __half* vs = ks + 2 * 128 * KSTRH;       // 2 bufs = 36864 B
    float* stl = (float*)(vs + 2 * 128 * VSTRH);  // 256 floats
    float* fls = stl + 256;                       // 64 floats

    const int t    = threadIdx.x;
    const int lane = t & 31;
    const int w    = t >> 5;       // 0..15
    const int g    = lane >> 2;
    const int t4   = lane & 3;
    const int mg   = w >> 2;       // rows mg*16..+15
    const int kg   = w & 3;        // keys kg*32..+31 within chunk
    const int bh   = blockIdx.y;
    const int q0   = blockIdx.x * QROWS;

    const uint32_t smem_b = (uint32_t)__cvta_generic_to_shared(smc);
    const uint32_t qs_b = smem_b;
    const uint32_t ks_b = smem_b + 64 * QSTRH * 2;
    const uint32_t vs_b = ks_b + 2 * KBUFB;

    const __half* kh  = g_kh + (size_t)bh * SEQ * DK;
    const __half* vh  = g_vh + (size_t)bh * SEQ * DK;

    // cp.async indices: 2 x 16B per thread for each of K, V (128 rows x 128 B)
    int srow[2], scol8[2];
#pragma unroll
    for (int r = 0; r < 2; ++r) {
        int lin = r * 512 + t;
        srow[r] = lin >> 3;            // 0..127
        scol8[r] = (lin & 7) * 8;      // halves
    }

    // stage Q + issue chunk-0 K/V loads
    {
        const __half* qb = g_qh + ((size_t)bh * SEQ + q0) * DK;
        const int r = t >> 3, c8 = (t & 7) * 8;
        *(uint4*)&qs[r * QSTRH + c8] = *(const uint4*)&qb[r * DK + c8];
    }
#pragma unroll
    for (int r = 0; r < 2; ++r) {
        cpa16(ks_b + (srow[r] * KSTRH + scol8[r]) * 2, kh + (size_t)srow[r] * DK + scol8[r]);
        cpa16(vs_b + (srow[r] * VSTRH + scol8[r]) * 2, vh + (size_t)srow[r] * DK + scol8[r]);
    }
    CPA_COMMIT();
    __syncthreads();   // qs visible

    // persistent Q A-fragments: 4 k16 blocks
    uint32_t afr[4][4];
    {
        const uint32_t qlane = qs_b +
            ((mg * 16 + (lane & 15)) * QSTRH) * 2 + (lane >> 4) * 16;
#pragma unroll
        for (int db = 0; db < 4; ++db) ldsm4(afr[db], qlane + db * 32);
    }

    // K B-frag lane base (non-trans): rows = keys, cols = d
    const uint32_t kfrag = ks_b +
        ((kg * 32 + (lane & 7) + ((lane >> 4) << 3)) * KSTRH) * 2 +
        ((lane >> 3) & 1) * 16;
    // V B-frag lane base (trans): rows = keys, cols = d
    const uint32_t vfrag = vs_b +
        ((kg * 32 + (lane & 7) + (((lane >> 3) & 1) << 3)) * VSTRH) * 2 +
        (lane >> 4) * 16;

    float lrow[2] = {0.f, 0.f};
    float oacc[8][4];
#pragma unroll
    for (int nb = 0; nb < 8; ++nb)
#pragma unroll
        for (int i = 0; i < 4; ++i) oacc[nb][i] = 0.f;

    float* attn_base = attn_out + ((size_t)bh * SEQ + q0) * SEQ;

    // ============== main loop: 1 barrier per chunk ==============
    for (int c = 0; c < NCH; ++c) {
        CPA_WAIT0();
        __syncthreads();
        if (c < NCH - 1) {
#pragma unroll
            for (int r = 0; r < 2; ++r) {
                cpa16(ks_b + ((c + 1) & 1) * KBUFB + (srow[r] * KSTRH + scol8[r]) * 2,
                      kh + ((size_t)(c + 1) * CHUNK + srow[r]) * DK + scol8[r]);
                cpa16(vs_b + ((c + 1) & 1) * VBUFB + (srow[r] * VSTRH + scol8[r]) * 2,
                      vh + ((size_t)(c + 1) * CHUNK + srow[r]) * DK + scol8[r]);
            }
            CPA_COMMIT();
        }

        // scores: 16 rows x 32 keys, K=64 (4 k16 blocks)
        const uint32_t kbb = kfrag + (c & 1) * KBUFB;
        float sacc[4][4];
#pragma unroll
        for (int nb = 0; nb < 4; ++nb)
#pragma unroll
            for (int i = 0; i < 4; ++i) sacc[nb][i] = 0.f;
#pragma unroll
        for (int db = 0; db < 4; ++db) {
#pragma unroll
            for (int pr = 0; pr < 2; ++pr) {
                uint32_t b[4];
                ldsm4(b, kbb + pr * (16 * KSTRH * 2) + db * 32);
                mmah(sacc[pr * 2],     afr[db], b[0], b[1]);
                mmah(sacc[pr * 2 + 1], afr[db], b[2], b[3]);
            }
        }

        // u = exp(s); row sums; P -> registers (fp16 A-frags) + gmem fp32
        uint32_t pa[2][4];
        float csum0 = 0.f, csum1 = 0.f;
#pragma unroll
        for (int nb = 0; nb < 4; ++nb) {
            const float u00 = __expf(sacc[nb][0]);
            const float u01 = __expf(sacc[nb][1]);
            const float u10 = __expf(sacc[nb][2]);
            const float u11 = __expf(sacc[nb][3]);
            csum0 += u00 + u01;
            csum1 += u10 + u11;
            pa[nb >> 1][(nb & 1) * 2]     = pack2h(u00, u01);
            pa[nb >> 1][(nb & 1) * 2 + 1] = pack2h(u10, u11);
            const int col = c * CHUNK + kg * 32 + nb * 8 + 2 * t4;
            *(float2*)&attn_base[(size_t)(mg * 16 + g) * SEQ + col] =
                make_float2(u00, u01);
            *(float2*)&attn_base[(size_t)(mg * 16 + g + 8) * SEQ + col] =
                make_float2(u10, u11);
        }
        csum0 += __shfl_xor_sync(~0u, csum0, 1);
        csum0 += __shfl_xor_sync(~0u, csum0, 2);
        csum1 += __shfl_xor_sync(~0u, csum1, 1);
        csum1 += __shfl_xor_sync(~0u, csum1, 2);
        lrow[0] += csum0;
        lrow[1] += csum1;

        // P @ V: A = pa (registers), B = V via ldsm.trans
        const uint32_t vbb = vfrag + (c & 1) * VBUFB;
#pragma unroll
        for (int kb2 = 0; kb2 < 2; ++kb2) {
#pragma unroll
            for (int dp = 0; dp < 4; ++dp) {
                uint32_t b[4];
                ldsm4t(b, vbb + kb2 * (16 * VSTRH * 2) + dp * 32);
                mmah(oacc[dp * 2],     pa[kb2], b[0], b[1]);
                mmah(oacc[dp * 2 + 1], pa[kb2], b[2], b[3]);
            }
        }
    }

    // ---- l reduce across 4 key-group warps ----
    if (t4 == 0) {
        stl[kg * 64 + mg * 16 + g]     = lrow[0];
        stl[kg * 64 + mg * 16 + g + 8] = lrow[1];
    }
    __syncthreads();
    if (t < 64) {
        float fl = 0.f;
#pragma unroll
        for (int q = 0; q < 4; ++q) fl += stl[q * 64 + t];
        fls[t] = 1.0f / fl;
    }
    __syncthreads();

    // ---- in-place fixup: scale u by 1/l (float4, L2-resident) ----
#pragma unroll 4
    for (int i = t; i < 64 * 512; i += 512) {
        const int row = i >> 9;
        const int c4  = (i & 511) * 4;
        float4 v = __ldcg((const float4*)&attn_base[(size_t)row * SEQ + c4]);
        const float s = fls[row];
        v.x *= s; v.y *= s; v.z *= s; v.w *= s;
        __stcs((float4*)&attn_base[(size_t)row * SEQ + c4], v);
    }

    // ---- O reduce across 4 key-group warps per m-group (scale by 1/l) ----
    __syncthreads();
    float* osm = (float*)smc;   // 16 warps x [16][68] = 69632 B (fits below stl)
#pragma unroll
    for (int nb = 0; nb < 8; ++nb) {
        const int oc = nb * 8 + 2 * t4;
        *(float2*)&osm[w * 1088 + g * 68 + oc]       = make_float2(oacc[nb][0], oacc[nb][1]);
        *(float2*)&osm[w * 1088 + (g + 8) * 68 + oc] = make_float2(oacc[nb][2], oacc[nb][3]);
    }
    __syncthreads();
    const int b = bh >> 4, h = bh & 15;
#pragma unroll
    for (int i = t; i < 4096; i += 512) {
        const int rr = i >> 6, d = i & 63;
        const int mg2 = rr >> 4, r16 = rr & 15;
        float s = 0.f;
#pragma unroll
        for (int q = 0; q < 4; ++q)
            s += osm[(mg2 * 4 + q) * 1088 + r16 * 68 + d];
        g_ctx[((size_t)b * SEQ + q0 + rr) * D_MODEL + h * DK + d] =
            f2tf(s * fls[rr]);
    }
}

// ---------------- launch -----------------------------------------------------
extern "C" void kernel_launch(void* const* d_in, const int* in_sizes, int n_in,
                              void* d_out, int out_size)
{
    (void)in_sizes; (void)n_in; (void)out_size;
    const float* q  = (const float*)d_in[0];
    const float* k  = (const float*)d_in[1];
    const float* v  = (const float*)d_in[2];
    const float* wq = (const float*)d_in[3];
    const float* bq = (const float*)d_in[4];
    const float* wk = (const float*)d_in[5];
    const float* bk = (const float*)d_in[6];
    const float* wv = (const float*)d_in[7];
    const float* bv = (const float*)d_in[8];
    const float* wo = (const float*)d_in[9];
    const float* bo = (const float*)d_in[10];

    float* out  = (float*)d_out;                       // [B,S,D]
    float* attn = out + (size_t)MROWS * D_MODEL;       // [B,H,S,S]

    const int asmem = 64 * QSTRH * 2 + 2 * KBUFB + 2 * VBUFB + (256 + 64) * 4; // 84224
    cudaFuncSetAttribute(attn_k, cudaFuncAttributeMaxDynamicSharedMemorySize, asmem);
    const int gsmem = NST * (ATILE + BTILE) * 4;   // 56832 B
    cudaFuncSetAttribute(qkv_gemm_p, cudaFuncAttributeMaxDynamicSharedMemorySize, gsmem);
    cudaFuncSetAttribute(out_gemm,   cudaFuncAttributeMaxDynamicSharedMemorySize, gsmem);

    cvt_inputs <<<dim3(MROWS * D_MODEL / (256 * 4), 3), 256>>>(q, k, v);
    cvt_weights<<<dim3(D_MODEL * D_MODEL / (256 * 4), 4), 256>>>(wq, wk, wv, wo);
    qkv_gemm_p<<<dim3(8, 32, 3), 256, gsmem>>>(bq, bk, bv);
    attn_k<<<dim3(SEQ / QROWS, NBH), 512, asmem>>>(attn);
    out_gemm<<<dim3(8, 32), 256, gsmem>>>(bo, out);
}

// round 14
// speedup vs baseline: 2.1092x; 1.3740x over previous
#include <cuda_runtime.h>
#include <cuda_fp16.h>
#include <cstdint>

#define D_MODEL 1024
#define NHEAD   16
#define DK      64
#define BB      2
#define SEQ     2048
#define MROWS   (BB * SEQ)   // 4096
#define NBH     (BB * NHEAD) // 32

// attention tiling
#define QROWS 64
#define CHUNK 128
#define NCH   (SEQ / CHUNK)  // 16

// attention smem strides in HALVES
#define QSTRH 72
#define KSTRH 72
#define VSTRH 72
#define KBUFB (128 * KSTRH * 2)   // 18432 B
#define VBUFB (128 * VSTRH * 2)   // 18432 B

// fp16 GEMM strides (halves) / pipeline
#define ASTRH 40                  // A tile [128 m][32 k]
#define BSTRH 136                 // B tile [32 k][128 n]
#define NST   3
#define ATILEH (128 * ASTRH)      // 5120 halves
#define BTILEH (32 * BSTRH)       // 4352 halves

// ---------------- scratch (device globals) -----------------------------------
__device__ __half g_qin[MROWS * D_MODEL];
__device__ __half g_kin[MROWS * D_MODEL];
__device__ __half g_vin[MROWS * D_MODEL];
__device__ __half g_wqc[D_MODEL * D_MODEL];
__device__ __half g_wkc[D_MODEL * D_MODEL];
__device__ __half g_wvc[D_MODEL * D_MODEL];
__device__ __half g_woc[D_MODEL * D_MODEL];
__device__ __half g_qh [NBH * SEQ * DK];   // [bh][s][d] fp16, pre-scaled 1/8
__device__ __half g_kh [NBH * SEQ * DK];   // [bh][s][d] fp16
__device__ __half g_vh [NBH * SEQ * DK];   // [bh][s][d] fp16
__device__ __half g_ctx[MROWS * D_MODEL];  // [b*S+s][h*64+d] fp16

// ---------------- helpers ----------------------------------------------------
__device__ __forceinline__ uint32_t pack2h(float a, float b) {
    __half2 h = __floats2half2_rn(a, b);
    return *(uint32_t*)&h;
}

// fp16 m16n8k16
__device__ __forceinline__ void mmah(float* d, const uint32_t* a,
                                     uint32_t b0, uint32_t b1) {
    asm volatile(
        "mma.sync.aligned.m16n8k16.row.col.f32.f16.f16.f32 "
        "{%0,%1,%2,%3}, {%4,%5,%6,%7}, {%8,%9}, {%0,%1,%2,%3};"
        : "+f"(d[0]), "+f"(d[1]), "+f"(d[2]), "+f"(d[3])
        : "r"(a[0]), "r"(a[1]), "r"(a[2]), "r"(a[3]), "r"(b0), "r"(b1));
}

__device__ __forceinline__ void ldsm4(uint32_t* r, uint32_t saddr) {
    asm volatile(
        "ldmatrix.sync.aligned.m8n8.x4.shared.b16 {%0,%1,%2,%3}, [%4];"
        : "=r"(r[0]), "=r"(r[1]), "=r"(r[2]), "=r"(r[3]) : "r"(saddr));
}

__device__ __forceinline__ void ldsm4t(uint32_t* r, uint32_t saddr) {
    asm volatile(
        "ldmatrix.sync.aligned.m8n8.x4.trans.shared.b16 {%0,%1,%2,%3}, [%4];"
        : "=r"(r[0]), "=r"(r[1]), "=r"(r[2]), "=r"(r[3]) : "r"(saddr));
}

__device__ __forceinline__ void cpa16(uint32_t dst, const void* src) {
    asm volatile("cp.async.cg.shared.global [%0], [%1], 16;"
                 :: "r"(dst), "l"(src) : "memory");
}
#define CPA_COMMIT() asm volatile("cp.async.commit_group;" ::: "memory")
#define CPA_WAIT1()  asm volatile("cp.async.wait_group 1;" ::: "memory")
#define CPA_WAIT0()  asm volatile("cp.async.wait_group 0;" ::: "memory")

// ---------------- pre-convert fp32 -> fp16 ------------------------------------
__global__ void __launch_bounds__(256) cvt_inputs(
    const float* __restrict__ q, const float* __restrict__ k,
    const float* __restrict__ v)
{
    const float* src = (blockIdx.y == 0) ? q : (blockIdx.y == 1) ? k : v;
    __half* dst = (blockIdx.y == 0) ? g_qin : (blockIdx.y == 1) ? g_kin : g_vin;
    const int i = (blockIdx.x * 256 + threadIdx.x) * 4;
    float4 f = *(const float4*)&src[i];
    uint2 o;
    o.x = pack2h(f.x, f.y);
    o.y = pack2h(f.z, f.w);
    *(uint2*)&dst[i] = o;
}

__global__ void __launch_bounds__(256) cvt_weights(
    const float* __restrict__ wq, const float* __restrict__ wk,
    const float* __restrict__ wv, const float* __restrict__ wo)
{
    const float* src = (blockIdx.y == 0) ? wq : (blockIdx.y == 1) ? wk
                     : (blockIdx.y == 2) ? wv : wo;
    __half* dst = (blockIdx.y == 0) ? g_wqc : (blockIdx.y == 1) ? g_wkc
                : (blockIdx.y == 2) ? g_wvc : g_woc;
    const int i = (blockIdx.x * 256 + threadIdx.x) * 4;
    float4 f = *(const float4*)&src[i];
    uint2 o;
    o.x = pack2h(f.x, f.y);
    o.y = pack2h(f.z, f.w);
    *(uint2*)&dst[i] = o;
}

// ---------------- fp16 tensor GEMM: 3-stage cp.async pipeline -----------------
// C[4096,1024] = A @ W + bias. CTA 128x128, kt=32, 256 thr (8 warps 4m x 2n).
// mode 0: fp32 row-major out; mode 1: fp16 qh (*0.125); mode 3: fp16 natural.
__device__ __forceinline__ void gemm_fp16(
    const __half* __restrict__ A, const __half* __restrict__ W,
    const float* __restrict__ bias, void* __restrict__ outp,
    int mode, __half* As, __half* Bs)
{
    const int t    = threadIdx.x;
    const int lane = t & 31;
    const int w    = t >> 5;
    const int g    = lane >> 2;
    const int t4   = lane & 3;
    const int bm   = blockIdx.y * 128;
    const int bn   = blockIdx.x * 128;
    const int wm   = (w >> 1) * 32;
    const int wn   = (w & 1) * 64;

    // staging indices: 2 x 16B per thread for each of A, B per stage
    int a_row[2], a_c8[2], b_row[2], b_c8[2];
#pragma unroll
    for (int r = 0; r < 2; ++r) {
        int lin = r * 256 + t;
        a_row[r] = lin >> 2;  a_c8[r] = (lin & 3) * 8;    // A: [128][32] halves
        b_row[r] = lin >> 4;  b_c8[r] = (lin & 15) * 8;   // B: [32][128] halves
    }

    const uint32_t as_b = (uint32_t)__cvta_generic_to_shared(As);
    const uint32_t bs_b = (uint32_t)__cvta_generic_to_shared(Bs);

    float acc[2][8][4];
#pragma unroll
    for (int mt = 0; mt < 2; ++mt)
#pragma unroll
        for (int nt = 0; nt < 8; ++nt)
#pragma unroll
            for (int i = 0; i < 4; ++i) acc[mt][nt][i] = 0.f;

    // prologue: stages 0, 1
#pragma unroll
    for (int s = 0; s < 2; ++s) {
        const int k0 = s * 32;
#pragma unroll
        for (int r = 0; r < 2; ++r) {
            cpa16(as_b + s * (ATILEH * 2) + (a_row[r] * ASTRH + a_c8[r]) * 2,
                  A + (size_t)(bm + a_row[r]) * 1024 + k0 + a_c8[r]);
            cpa16(bs_b + s * (BTILEH * 2) + (b_row[r] * BSTRH + b_c8[r]) * 2,
                  W + (size_t)(k0 + b_row[r]) * 1024 + bn + b_c8[r]);
        }
        CPA_COMMIT();
    }

    for (int it = 0; it < 32; ++it) {
        if (it < 30) { CPA_WAIT1(); } else { CPA_WAIT0(); }
        __syncthreads();
        const int stage = it % NST;
        const uint32_t abase = as_b + stage * (ATILEH * 2);
        const uint32_t bbase = bs_b + stage * (BTILEH * 2);
#pragma unroll
        for (int ks = 0; ks < 2; ++ks) {
            uint32_t af[2][4];
#pragma unroll
            for (int mt = 0; mt < 2; ++mt)
                ldsm4(af[mt], abase +
                      ((wm + mt * 16 + (lane & 15)) * ASTRH) * 2 +
                      (lane >> 4) * 16 + ks * 32);
#pragma unroll
            for (int dp = 0; dp < 4; ++dp) {
                uint32_t b[4];
                ldsm4t(b, bbase +
                       ((ks * 16 + (lane & 7) + (((lane >> 3) & 1) << 3)) * BSTRH) * 2 +
                       (lane >> 4) * 16 + (wn + dp * 16) * 2);
                mmah(acc[0][dp * 2],     af[0], b[0], b[1]);
                mmah(acc[0][dp * 2 + 1], af[0], b[2], b[3]);
                mmah(acc[1][dp * 2],     af[1], b[0], b[1]);
                mmah(acc[1][dp * 2 + 1], af[1], b[2], b[3]);
            }
        }
        if (it < 30) {
            const int s2 = (it + 2) % NST;
            const int k0 = (it + 2) * 32;
#pragma unroll
            for (int r = 0; r < 2; ++r) {
                cpa16(as_b + s2 * (ATILEH * 2) + (a_row[r] * ASTRH + a_c8[r]) * 2,
                      A + (size_t)(bm + a_row[r]) * 1024 + k0 + a_c8[r]);
                cpa16(bs_b + s2 * (BTILEH * 2) + (b_row[r] * BSTRH + b_c8[r]) * 2,
                      W + (size_t)(k0 + b_row[r]) * 1024 + bn + b_c8[r]);
            }
            CPA_COMMIT();
        }
    }

    // ---- epilogue ----
#pragma unroll
    for (int mt = 0; mt < 2; ++mt) {
        const int m0 = bm + wm + mt * 16 + g;
#pragma unroll
        for (int nt = 0; nt < 8; ++nt) {
            const int n0 = bn + wn + nt * 8 + 2 * t4;
            const float bz0 = bias[n0], bz1 = bias[n0 + 1];
            float v00 = acc[mt][nt][0] + bz0;
            float v01 = acc[mt][nt][1] + bz1;
            float v10 = acc[mt][nt][2] + bz0;
            float v11 = acc[mt][nt][3] + bz1;
            if (mode == 0) {
                float* out = (float*)outp;
                *(float2*)&out[(size_t)m0 * 1024 + n0]       = make_float2(v00, v01);
                *(float2*)&out[(size_t)(m0 + 8) * 1024 + n0] = make_float2(v10, v11);
            } else {
                __half* out = (__half*)outp;
                const int b0i = m0 >> 11, s0 = m0 & 2047;
                const int h = n0 >> 6, d = n0 & 63;
                const int bh = b0i * NHEAD + h;
                const float sc = (mode == 1) ? 0.125f : 1.0f;
                *(__half2*)&out[((size_t)bh * SEQ + s0) * DK + d] =
                    __floats2half2_rn(v00 * sc, v01 * sc);
                *(__half2*)&out[((size_t)bh * SEQ + s0 + 8) * DK + d] =
                    __floats2half2_rn(v10 * sc, v11 * sc);
            }
        }
    }
}

__global__ void __launch_bounds__(256, 2) qkv_gemm_p(
    const float* __restrict__ bq, const float* __restrict__ bk,
    const float* __restrict__ bv)
{
    extern __shared__ __half gsm[];
    __half* As = gsm;
    __half* Bs = gsm + NST * ATILEH;
    const int z = blockIdx.z;
    const __half* A      = (z == 0) ? g_qin : (z == 1) ? g_kin : g_vin;
    const __half* W      = (z == 0) ? g_wqc : (z == 1) ? g_wkc : g_wvc;
    const float*  bias   = (z == 0) ? bq    : (z == 1) ? bk    : bv;
    void* out            = (z == 0) ? (void*)g_qh : (z == 1) ? (void*)g_kh : (void*)g_vh;
    gemm_fp16(A, W, bias, out, (z == 0) ? 1 : 3, As, Bs);
}

__global__ void __launch_bounds__(256, 2) out_gemm(
    const float* __restrict__ bo, float* __restrict__ out)
{
    extern __shared__ __half gsm[];
    __half* As = gsm;
    __half* Bs = gsm + NST * ATILEH;
    gemm_fp16(g_ctx, g_woc, bo, out, 0, As, Bs);
}

// ---------------- attention: fp16 single-pass, P in registers (R13) -----------
__global__ void __launch_bounds__(512) attn_k(float* __restrict__ attn_out)
{
    extern __shared__ char smc[];
    __half* qs = (__half*)smc;               // 64*QSTRH halves = 9216 B
    __half* ks = qs + 64 * QSTRH;            // 2 bufs = 36864 B
    __half* vs = ks + 2 * 128 * KSTRH;       // 2 bufs = 36864 B
    float* stl = (float*)(vs + 2 * 128 * VSTRH);  // 256 floats
    float* fls = stl + 256;                       // 64 floats

    const int t    = threadIdx.x;
    const int lane = t & 31;
    const int w    = t >> 5;
    const int g    = lane >> 2;
    const int t4   = lane & 3;
    const int mg   = w >> 2;
    const int kg   = w & 3;
    const int bh   = blockIdx.y;
    const int q0   = blockIdx.x * QROWS;

    const uint32_t smem_b = (uint32_t)__cvta_generic_to_shared(smc);
    const uint32_t qs_b = smem_b;
    const uint32_t ks_b = smem_b + 64 * QSTRH * 2;
    const uint32_t vs_b = ks_b + 2 * KBUFB;

    const __half* kh  = g_kh + (size_t)bh * SEQ * DK;
    const __half* vh  = g_vh + (size_t)bh * SEQ * DK;

    int srow[2], scol8[2];
#pragma unroll
    for (int r = 0; r < 2; ++r) {
        int lin = r * 512 + t;
        srow[r] = lin >> 3;
        scol8[r] = (lin & 7) * 8;
    }

    {
        const __half* qb = g_qh + ((size_t)bh * SEQ + q0) * DK;
        const int r = t >> 3, c8 = (t & 7) * 8;
        *(uint4*)&qs[r * QSTRH + c8] = *(const uint4*)&qb[r * DK + c8];
    }
#pragma unroll
    for (int r = 0; r < 2; ++r) {
        cpa16(ks_b + (srow[r] * KSTRH + scol8[r]) * 2, kh + (size_t)srow[r] * DK + scol8[r]);
        cpa16(vs_b + (srow[r] * VSTRH + scol8[r]) * 2, vh + (size_t)srow[r] * DK + scol8[r]);
    }
    CPA_COMMIT();
    __syncthreads();

    uint32_t afr[4][4];
    {
        const uint32_t qlane = qs_b +
            ((mg * 16 + (lane & 15)) * QSTRH) * 2 + (lane >> 4) * 16;
#pragma unroll
        for (int db = 0; db < 4; ++db) ldsm4(afr[db], qlane + db * 32);
    }

    const uint32_t kfrag = ks_b +
        ((kg * 32 + (lane & 7) + ((lane >> 4) << 3)) * KSTRH) * 2 +
        ((lane >> 3) & 1) * 16;
    const uint32_t vfrag = vs_b +
        ((kg * 32 + (lane & 7) + (((lane >> 3) & 1) << 3)) * VSTRH) * 2 +
        (lane >> 4) * 16;

    float lrow[2] = {0.f, 0.f};
    float oacc[8][4];
#pragma unroll
    for (int nb = 0; nb < 8; ++nb)
#pragma unroll
        for (int i = 0; i < 4; ++i) oacc[nb][i] = 0.f;

    float* attn_base = attn_out + ((size_t)bh * SEQ + q0) * SEQ;

    for (int c = 0; c < NCH; ++c) {
        CPA_WAIT0();
        __syncthreads();
        if (c < NCH - 1) {
#pragma unroll
            for (int r = 0; r < 2; ++r) {
                cpa16(ks_b + ((c + 1) & 1) * KBUFB + (srow[r] * KSTRH + scol8[r]) * 2,
                      kh + ((size_t)(c + 1) * CHUNK + srow[r]) * DK + scol8[r]);
                cpa16(vs_b + ((c + 1) & 1) * VBUFB + (srow[r] * VSTRH + scol8[r]) * 2,
                      vh + ((size_t)(c + 1) * CHUNK + srow[r]) * DK + scol8[r]);
            }
            CPA_COMMIT();
        }

        const uint32_t kbb = kfrag + (c & 1) * KBUFB;
        float sacc[4][4];
#pragma unroll
        for (int nb = 0; nb < 4; ++nb)
#pragma unroll
            for (int i = 0; i < 4; ++i) sacc[nb][i] = 0.f;
#pragma unroll
        for (int db = 0; db < 4; ++db) {
#pragma unroll
            for (int pr = 0; pr < 2; ++pr) {
                uint32_t b[4];
                ldsm4(b, kbb + pr * (16 * KSTRH * 2) + db * 32);
                mmah(sacc[pr * 2],     afr[db], b[0], b[1]);
                mmah(sacc[pr * 2 + 1], afr[db], b[2], b[3]);
            }
        }

        uint32_t pa[2][4];
        float csum0 = 0.f, csum1 = 0.f;
#pragma unroll
        for (int nb = 0; nb < 4; ++nb) {
            const float u00 = __expf(sacc[nb][0]);
            const float u01 = __expf(sacc[nb][1]);
            const float u10 = __expf(sacc[nb][2]);
            const float u11 = __expf(sacc[nb][3]);
            csum0 += u00 + u01;
            csum1 += u10 + u11;
            pa[nb >> 1][(nb & 1) * 2]     = pack2h(u00, u01);
            pa[nb >> 1][(nb & 1) * 2 + 1] = pack2h(u10, u11);
            const int col = c * CHUNK + kg * 32 + nb * 8 + 2 * t4;
            *(float2*)&attn_base[(size_t)(mg * 16 + g) * SEQ + col] =
                make_float2(u00, u01);
            *(float2*)&attn_base[(size_t)(mg * 16 + g + 8) * SEQ + col] =
                make_float2(u10, u11);
        }
        csum0 += __shfl_xor_sync(~0u, csum0, 1);
        csum0 += __shfl_xor_sync(~0u, csum0, 2);
        csum1 += __shfl_xor_sync(~0u, csum1, 1);
        csum1 += __shfl_xor_sync(~0u, csum1, 2);
        lrow[0] += csum0;
        lrow[1] += csum1;

        const uint32_t vbb = vfrag + (c & 1) * VBUFB;
#pragma unroll
        for (int kb2 = 0; kb2 < 2; ++kb2) {
#pragma unroll
            for (int dp = 0; dp < 4; ++dp) {
                uint32_t b[4];
                ldsm4t(b, vbb + kb2 * (16 * VSTRH * 2) + dp * 32);
                mmah(oacc[dp * 2],     pa[kb2], b[0], b[1]);
                mmah(oacc[dp * 2 + 1], pa[kb2], b[2], b[3]);
            }
        }
    }

    if (t4 == 0) {
        stl[kg * 64 + mg * 16 + g]     = lrow[0];
        stl[kg * 64 + mg * 16 + g + 8] = lrow[1];
    }
    __syncthreads();
    if (t < 64) {
        float fl = 0.f;
#pragma unroll
        for (int q = 0; q < 4; ++q) fl += stl[q * 64 + t];
        fls[t] = 1.0f / fl;
    }
    __syncthreads();

#pragma unroll 4
    for (int i = t; i < 64 * 512; i += 512) {
        const int row = i >> 9;
        const int c4  = (i & 511) * 4;
        float4 v = __ldcg((const float4*)&attn_base[(size_t)row * SEQ + c4]);
        const float s = fls[row];
        v.x *= s; v.y *= s; v.z *= s; v.w *= s;
        __stcs((float4*)&attn_base[(size_t)row * SEQ + c4], v);
    }

    __syncthreads();
    float* osm = (float*)smc;   // 16 warps x [16][68]
#pragma unroll
    for (int nb = 0; nb < 8; ++nb) {
        const int oc = nb * 8 + 2 * t4;
        *(float2*)&osm[w * 1088 + g * 68 + oc]       = make_float2(oacc[nb][0], oacc[nb][1]);
        *(float2*)&osm[w * 1088 + (g + 8) * 68 + oc] = make_float2(oacc[nb][2], oacc[nb][3]);
    }
    __syncthreads();
    const int b = bh >> 4, h = bh & 15;
#pragma unroll
    for (int i = t; i < 4096; i += 512) {
        const int rr = i >> 6, d = i & 63;
        const int mg2 = rr >> 4, r16 = rr & 15;
        float s = 0.f;
#pragma unroll
        for (int q = 0; q < 4; ++q)
            s += osm[(mg2 * 4 + q) * 1088 + r16 * 68 + d];
        g_ctx[((size_t)b * SEQ + q0 + rr) * D_MODEL + h * DK + d] =
            __float2half(s * fls[rr]);
    }
}

// ---------------- launch -----------------------------------------------------
extern "C" void kernel_launch(void* const* d_in, const int* in_sizes, int n_in,
                              void* d_out, int out_size)
{
    (void)in_sizes; (void)n_in; (void)out_size;
    const float* q  = (const float*)d_in[0];
    const float* k  = (const float*)d_in[1];
    const float* v  = (const float*)d_in[2];
    const float* wq = (const float*)d_in[3];
    const float* bq = (const float*)d_in[4];
    const float* wk = (const float*)d_in[5];
    const float* bk = (const float*)d_in[6];
    const float* wv = (const float*)d_in[7];
    const float* bv = (const float*)d_in[8];
    const float* wo = (const float*)d_in[9];
    const float* bo = (const float*)d_in[10];

    float* out  = (float*)d_out;                       // [B,S,D]
    float* attn = out + (size_t)MROWS * D_MODEL;       // [B,H,S,S]

    const int asmem = 64 * QSTRH * 2 + 2 * KBUFB + 2 * VBUFB + (256 + 64) * 4; // 84224
    cudaFuncSetAttribute(attn_k, cudaFuncAttributeMaxDynamicSharedMemorySize, asmem);
    const int gsmem = NST * (ATILEH + BTILEH) * 2;   // 56832 B
    cudaFuncSetAttribute(qkv_gemm_p, cudaFuncAttributeMaxDynamicSharedMemorySize, gsmem);
    cudaFuncSetAttribute(out_gemm,   cudaFuncAttributeMaxDynamicSharedMemorySize, gsmem);

    cvt_inputs <<<dim3(MROWS * D_MODEL / (256 * 4), 3), 256>>>(q, k, v);
    cvt_weights<<<dim3(D_MODEL * D_MODEL / (256 * 4), 4), 256>>>(wq, wk, wv, wo);
    qkv_gemm_p<<<dim3(8, 32, 3), 256, gsmem>>>(bq, bk, bv);
    attn_k<<<dim3(SEQ / QROWS, NBH), 512, asmem>>>(attn);
    out_gemm<<<dim3(8, 32), 256, gsmem>>>(bo, out);
}